// round 5
// baseline (speedup 1.0000x reference)
#include <cuda_runtime.h>
#include <cuda_bf16.h>
#include <math.h>
#include <stdint.h>

#define D_MODEL 1024
#define NH      16
#define DK      64
#define BATCH   2
#define SEQ     1024
#define BHT     (BATCH*NH)          // 32
#define MTOT    (BATCH*SEQ)         // 2048
#define ELEN    (2*SEQ-1)           // 2047

// ---------------- scratch (device globals; no allocation allowed) ----------
__device__ __nv_bfloat16 g_xh[MTOT*D_MODEL];
__device__ __nv_bfloat16 g_xl[MTOT*D_MODEL];
__device__ __nv_bfloat16 g_wh[4*D_MODEL*D_MODEL];  // Wq|Wk|Wv|Wo stacked rows
__device__ __nv_bfloat16 g_wl[4*D_MODEL*D_MODEL];
__device__ __nv_bfloat16 g_oh[MTOT*D_MODEL];
__device__ __nv_bfloat16 g_ol[MTOT*D_MODEL];

__device__ __nv_bfloat16 g_Qh[BHT*SEQ*DK];   // [bh][s][d], pre-scaled 1/8
__device__ __nv_bfloat16 g_Ql[BHT*SEQ*DK];
__device__ __nv_bfloat16 g_Kh[BHT*SEQ*DK];
__device__ __nv_bfloat16 g_Kl[BHT*SEQ*DK];
__device__ __nv_bfloat16 g_Vth[BHT*DK*SEQ];  // [bh][d][s]  (transposed)
__device__ __nv_bfloat16 g_Vtl[BHT*DK*SEQ];
__device__ __nv_bfloat16 g_Eh[ELEN*DK];
__device__ __nv_bfloat16 g_El[ELEN*DK];

// ---------------- helpers ---------------------------------------------------
__device__ __forceinline__ uint32_t smem_u32(const void* p) {
    uint32_t a;
    asm("{ .reg .u64 t; cvta.to.shared.u64 t, %1; cvt.u32.u64 %0, t; }"
        : "=r"(a) : "l"(p));
    return a;
}

#define CP16(dst_u32, src_ptr) \
    asm volatile("cp.async.cg.shared.global [%0], [%1], 16;" \
                 :: "r"(dst_u32), "l"(src_ptr) : "memory")
#define CP_COMMIT() asm volatile("cp.async.commit_group;" ::: "memory")
#define CP_WAIT0()  asm volatile("cp.async.wait_group 0;" ::: "memory")

#define LDMATRIX_X4(r0, r1, r2, r3, addr) \
    asm volatile("ldmatrix.sync.aligned.m8n8.x4.shared.b16 {%0,%1,%2,%3}, [%4];" \
                 : "=r"(r0), "=r"(r1), "=r"(r2), "=r"(r3) : "r"(addr))

#define MMA_BF16(c, a, b) \
    asm volatile("mma.sync.aligned.m16n8k16.row.col.f32.bf16.bf16.f32 " \
                 "{%0,%1,%2,%3}, {%4,%5,%6,%7}, {%8,%9}, {%0,%1,%2,%3};" \
                 : "+f"((c)[0]), "+f"((c)[1]), "+f"((c)[2]), "+f"((c)[3]) \
                 : "r"((a)[0]), "r"((a)[1]), "r"((a)[2]), "r"((a)[3]), \
                   "r"((b)[0]), "r"((b)[1]))

__device__ __forceinline__ uint32_t pack_bf2(float lo, float hi) {
    __nv_bfloat162 t = __floats2bfloat162_rn(lo, hi);
    return *(uint32_t*)&t;
}
__device__ __forceinline__ void split_bf(float v, __nv_bfloat16& h, __nv_bfloat16& l) {
    h = __float2bfloat16_rn(v);
    l = __float2bfloat16_rn(v - __bfloat162float(h));
}

// ---------------------------------------------------------------------------
// fp32 -> bf16 hi/lo split conversion (x, 4 weights, Er)
// ---------------------------------------------------------------------------
__global__ void convert_xw_kernel(const float* __restrict__ x,
                                  const float* __restrict__ Wq, const float* __restrict__ Wk,
                                  const float* __restrict__ Wv, const float* __restrict__ Wo,
                                  const float* __restrict__ Er)
{
    const int NX = MTOT * D_MODEL / 4;
    const int NW = D_MODEL * D_MODEL / 4;
    const int NE = ELEN * DK / 4;
    int g = blockIdx.x * blockDim.x + threadIdx.x;
    if (g >= NX + 4 * NW + NE) return;
    const float* src;
    __nv_bfloat16 *dh, *dl;
    if (g < NX) { src = x + g * 4; dh = g_xh + g * 4; dl = g_xl + g * 4; }
    else if (g < NX + 4 * NW) {
        int wi = g - NX;
        int which = wi / NW;
        int off = wi - which * NW;
        const float* W = (which == 0) ? Wq : (which == 1) ? Wk : (which == 2) ? Wv : Wo;
        src = W + off * 4;
        dh = g_wh + (size_t)which * NW * 4 + off * 4;
        dl = g_wl + (size_t)which * NW * 4 + off * 4;
    } else {
        int ei = g - NX - 4 * NW;
        src = Er + ei * 4; dh = g_Eh + ei * 4; dl = g_El + ei * 4;
    }
    float4 v = *(const float4*)src;
    __nv_bfloat16 hv[4], lv[4];
    split_bf(v.x, hv[0], lv[0]); split_bf(v.y, hv[1], lv[1]);
    split_bf(v.z, hv[2], lv[2]); split_bf(v.w, hv[3], lv[3]);
    *(uint2*)dh = *(uint2*)hv;
    *(uint2*)dl = *(uint2*)lv;
}

// ---------------------------------------------------------------------------
// Split-bf16 mma.sync GEMM with cp.async 2-stage pipeline.
// ---------------------------------------------------------------------------
#define HSTR 40
#define MAT_HALVES (128*HSTR)
#define BUF_HALVES (4*MAT_HALVES)
#define GEMM_DYN_SMEM (2*BUF_HALVES*2)        // 81920 B

__global__ __launch_bounds__(256, 1)
void gemm_bf16_kernel(const __nv_bfloat16* __restrict__ Ah, const __nv_bfloat16* __restrict__ Al,
                      const __nv_bfloat16* __restrict__ Bh, const __nv_bfloat16* __restrict__ Bl,
                      const float* __restrict__ bias0, const float* __restrict__ bias1,
                      const float* __restrict__ bias2,
                      float* __restrict__ Cout, int mode)
{
    extern __shared__ __nv_bfloat16 sm[];

    const int tid  = threadIdx.x;
    const int wid  = tid >> 5;
    const int lane = tid & 31;
    const int warp_m = wid >> 2;
    const int warp_n = wid & 3;
    const int m0 = blockIdx.y * 128;
    const int n0 = blockIdx.x * 128;
    const int which = n0 >> 10;
    const int n0m = n0 & 1023;
    const float* biasm = (which == 0) ? bias0 : (which == 1) ? bias1 : bias2;

    float acc[4][4][4];
#pragma unroll
    for (int f = 0; f < 4; f++)
#pragma unroll
        for (int g = 0; g < 4; g++)
#pragma unroll
            for (int e = 0; e < 4; e++) acc[f][g][e] = 0.f;

    const int lrow = tid >> 2;
    const int lk   = (tid & 3) * 8;
    const uint32_t smb = smem_u32(sm);

    // issue chunk c into buffer buf
    auto issue = [&](int c, int buf) {
        uint32_t bb = smb + buf * BUF_HALVES * 2;
        int kg = c * 32 + lk;
#pragma unroll
        for (int i = 0; i < 2; i++) {
            int row = lrow + i * 64;
            uint32_t doff = (row * HSTR + lk) * 2;
            CP16(bb + 0 * MAT_HALVES * 2 + doff, Ah + (size_t)(m0 + row) * 1024 + kg);
            CP16(bb + 1 * MAT_HALVES * 2 + doff, Al + (size_t)(m0 + row) * 1024 + kg);
            CP16(bb + 2 * MAT_HALVES * 2 + doff, Bh + (size_t)(n0 + row) * 1024 + kg);
            CP16(bb + 3 * MAT_HALVES * 2 + doff, Bl + (size_t)(n0 + row) * 1024 + kg);
        }
        CP_COMMIT();
    };

    issue(0, 0);

    const int a_r   = lane & 15;
    const int a_kof = (lane >> 4) * 8;

    for (int c = 0; c < 32; c++) {
        CP_WAIT0();
        __syncthreads();
        if (c < 31) issue(c + 1, (c + 1) & 1);

        __nv_bfloat16* cb = sm + (c & 1) * BUF_HALVES;
#pragma unroll
        for (int ks = 0; ks < 2; ks++) {
            uint32_t aH[4][4], aL[4][4], bH[4][2], bL[4][2];
#pragma unroll
            for (int f = 0; f < 4; f++) {
                int row = warp_m * 64 + f * 16 + a_r;
                uint32_t addrH = smem_u32(&cb[0 * MAT_HALVES + row * HSTR + ks * 16 + a_kof]);
                LDMATRIX_X4(aH[f][0], aH[f][1], aH[f][2], aH[f][3], addrH);
                uint32_t addrL = smem_u32(&cb[1 * MAT_HALVES + row * HSTR + ks * 16 + a_kof]);
                LDMATRIX_X4(aL[f][0], aL[f][1], aL[f][2], aL[f][3], addrL);
            }
#pragma unroll
            for (int g = 0; g < 4; g++) {
                int n = warp_n * 32 + g * 8 + (lane >> 2);
                int off = n * HSTR + ks * 16 + (lane & 3) * 2;
                bH[g][0] = *(const uint32_t*)&cb[2 * MAT_HALVES + off];
                bH[g][1] = *(const uint32_t*)&cb[2 * MAT_HALVES + off + 8];
                bL[g][0] = *(const uint32_t*)&cb[3 * MAT_HALVES + off];
                bL[g][1] = *(const uint32_t*)&cb[3 * MAT_HALVES + off + 8];
            }
#pragma unroll
            for (int f = 0; f < 4; f++)
#pragma unroll
                for (int g = 0; g < 4; g++) {
                    MMA_BF16(acc[f][g], aH[f], bH[g]);
                    MMA_BF16(acc[f][g], aH[f], bL[g]);
                    MMA_BF16(acc[f][g], aL[f], bH[g]);
                }
        }
        __syncthreads();
    }

    if (mode == 0) {
        const float scale = (which == 0) ? 0.125f : 1.0f;
#pragma unroll
        for (int f = 0; f < 4; f++) {
            int mrow0 = m0 + warp_m * 64 + f * 16 + (lane >> 2);
#pragma unroll
            for (int g = 0; g < 4; g++) {
                int ncol = n0m + warp_n * 32 + g * 8 + (lane & 3) * 2;
#pragma unroll
                for (int e = 0; e < 4; e++) {
                    int m = mrow0 + (e >> 1) * 8;
                    int nm = ncol + (e & 1);
                    int b = m >> 10, s = m & 1023;
                    int h = nm >> 6, d = nm & 63;
                    float val = (acc[f][g][e] + biasm[nm]) * scale;
                    __nv_bfloat16 vh, vl;
                    split_bf(val, vh, vl);
                    if (which == 2) {
                        size_t idx = ((size_t)(b * NH + h) * DK + d) * SEQ + s;
                        g_Vth[idx] = vh; g_Vtl[idx] = vl;
                    } else if (which == 0) {
                        size_t idx = ((size_t)(b * NH + h) * SEQ + s) * DK + d;
                        g_Qh[idx] = vh; g_Ql[idx] = vl;
                    } else {
                        size_t idx = ((size_t)(b * NH + h) * SEQ + s) * DK + d;
                        g_Kh[idx] = vh; g_Kl[idx] = vl;
                    }
                }
            }
        }
    } else {
#pragma unroll
        for (int f = 0; f < 4; f++) {
            int mrow0 = m0 + warp_m * 64 + f * 16 + (lane >> 2);
#pragma unroll
            for (int g = 0; g < 4; g++) {
                int ncol = n0 + warp_n * 32 + g * 8 + (lane & 3) * 2;
#pragma unroll
                for (int e = 0; e < 4; e++) {
                    int m = mrow0 + (e >> 1) * 8;
                    int n = ncol + (e & 1);
                    Cout[(size_t)m * D_MODEL + n] = acc[f][g][e] + biasm[n];
                }
            }
        }
    }
}

// ---------------------------------------------------------------------------
// MMA flash-attention with band-limited G, cp.async loads, occupancy 2.
// CTA: 128 threads (4 warps), one (b,h), 64 query rows; 16 key tiles of 64.
// ---------------------------------------------------------------------------
#define ASTR 72
#define GBSTR 84
// smem: K/V hi+lo 4*64*72, E hi+lo 2*128*72 (bf16), G 4 warps x 16 x 84 fp32
#define ATTN_SMEM (4*64*ASTR*2 + 2*128*ASTR*2 + 4*16*GBSTR*4)   // 95232 B

__global__ __launch_bounds__(128, 2)
void attn_mma_kernel()
{
    extern __shared__ char smraw[];
    __nv_bfloat16* sKh = (__nv_bfloat16*)smraw;        // [j][d] pad 72
    __nv_bfloat16* sKl = sKh + 64 * ASTR;
    __nv_bfloat16* sVh = sKl + 64 * ASTR;              // [d][j] pad 72
    __nv_bfloat16* sVl = sVh + 64 * ASTR;
    __nv_bfloat16* sEh = sVl + 64 * ASTR;              // [r][d] pad 72, 128 rows
    __nv_bfloat16* sEl = sEh + 128 * ASTR;
    float* sG = (float*)(sEl + 128 * ASTR);            // per-warp 16 x 84
    __nv_bfloat16* sQh = (__nv_bfloat16*)sG;           // staging overlay (18KB<21KB)
    __nv_bfloat16* sQl = sQh + 64 * ASTR;

    const int tid  = threadIdx.x;
    const int lane = tid & 31;
    const int w    = tid >> 5;
    const int bh = blockIdx.y;
    const int i0 = blockIdx.x * 64;
    const int b = bh >> 4, h = bh & 15;

    const __nv_bfloat16* Qhg = g_Qh + (size_t)bh * SEQ * DK;
    const __nv_bfloat16* Qlg = g_Ql + (size_t)bh * SEQ * DK;
    const __nv_bfloat16* Khg = g_Kh + (size_t)bh * SEQ * DK;
    const __nv_bfloat16* Klg = g_Kl + (size_t)bh * SEQ * DK;
    const __nv_bfloat16* Vhg = g_Vth + (size_t)bh * DK * SEQ;
    const __nv_bfloat16* Vlg = g_Vtl + (size_t)bh * DK * SEQ;

    // stage Q once, load A-fragments to registers
    for (int t = tid; t < 512; t += 128) {
        int r = t >> 3, c8 = (t & 7) * 8;
        *(uint4*)&sQh[r * ASTR + c8] = *(const uint4*)(Qhg + (size_t)(i0 + r) * DK + c8);
        *(uint4*)&sQl[r * ASTR + c8] = *(const uint4*)(Qlg + (size_t)(i0 + r) * DK + c8);
    }
    __syncthreads();
    uint32_t qh[4][4], ql[4][4];
#pragma unroll
    for (int ks = 0; ks < 4; ks++) {
        uint32_t aH = smem_u32(&sQh[(w * 16 + (lane & 15)) * ASTR + ks * 16 + (lane >> 4) * 8]);
        LDMATRIX_X4(qh[ks][0], qh[ks][1], qh[ks][2], qh[ks][3], aH);
        uint32_t aL = smem_u32(&sQl[(w * 16 + (lane & 15)) * ASTR + ks * 16 + (lane >> 4) * 8]);
        LDMATRIX_X4(ql[ks][0], ql[ks][1], ql[ks][2], ql[ks][3], aL);
    }

    float accO[8][4];
#pragma unroll
    for (int nf = 0; nf < 8; nf++)
#pragma unroll
        for (int e = 0; e < 4; e++) accO[nf][e] = 0.f;
    float rmax0 = -1e30f, rmax1 = -1e30f, rsum0 = 0.f, rsum1 = 0.f;

    const int r0 = lane >> 2;
    const int c0 = (lane & 3) * 2;
    float* sGw = sG + w * 16 * GBSTR;
    const uint32_t sKh_u = smem_u32(sKh), sKl_u = smem_u32(sKl);
    const uint32_t sVh_u = smem_u32(sVh), sVl_u = smem_u32(sVl);
    const uint32_t sEh_u = smem_u32(sEh), sEl_u = smem_u32(sEl);

    for (int jt = 0; jt < 16; jt++) {
        const int j0 = jt * 64;
        __syncthreads();   // everyone done with prev K/V/E (and Q ldmatrix)

        // cp.async loads: K/V (4 arrays, 64x64) and E band (128 rows hi+lo)
        for (int t = tid; t < 512; t += 128) {
            int r = t >> 3, c8 = (t & 7) * 8;
            uint32_t doff = (r * ASTR + c8) * 2;
            CP16(sKh_u + doff, Khg + (size_t)(j0 + r) * DK + c8);
            CP16(sKl_u + doff, Klg + (size_t)(j0 + r) * DK + c8);
            CP16(sVh_u + doff, Vhg + (size_t)r * SEQ + j0 + c8);
            CP16(sVl_u + doff, Vlg + (size_t)r * SEQ + j0 + c8);
        }
        const int rbase = (SEQ - 1) + i0 - j0 - 63;
        for (int t = tid; t < 1024; t += 128) {
            int r = t >> 3, c8 = (t & 7) * 8;
            int rr = (r == 127) ? 126 : r;       // row 127 never gathered; keep in-bounds
            uint32_t doff = (r * ASTR + c8) * 2;
            CP16(sEh_u + doff, g_Eh + (size_t)(rbase + rr) * DK + c8);
            CP16(sEl_u + doff, g_El + (size_t)(rbase + rr) * DK + c8);
        }
        CP_COMMIT();
        CP_WAIT0();
        __syncthreads();

        // ---- G = Q * Eband^T, band-limited: nf in [2w, 2w+10) ----
        float gac[10][4];
#pragma unroll
        for (int bi = 0; bi < 10; bi++)
#pragma unroll
            for (int e = 0; e < 4; e++) gac[bi][e] = 0.f;
#pragma unroll
        for (int ks = 0; ks < 4; ks++) {
#pragma unroll
            for (int bi = 0; bi < 10; bi++) {
                int nf = 2 * w + bi;
                uint32_t beh[2], bel[2];
                int off = (nf * 8 + r0) * ASTR + ks * 16 + c0;
                beh[0] = *(const uint32_t*)&sEh[off];
                beh[1] = *(const uint32_t*)&sEh[off + 8];
                bel[0] = *(const uint32_t*)&sEl[off];
                bel[1] = *(const uint32_t*)&sEl[off + 8];
                MMA_BF16(gac[bi], qh[ks], beh);
                MMA_BF16(gac[bi], qh[ks], bel);
                MMA_BF16(gac[bi], ql[ks], beh);
            }
        }
        // store band (cols bi*8+c0 local to warp)
#pragma unroll
        for (int bi = 0; bi < 10; bi++) {
            *(float2*)&sGw[r0 * GBSTR + bi * 8 + c0] = make_float2(gac[bi][0], gac[bi][1]);
            *(float2*)&sGw[(r0 + 8) * GBSTR + bi * 8 + c0] = make_float2(gac[bi][2], gac[bi][3]);
        }

        // ---- S = Q * K^T ----
        float s[8][4];
#pragma unroll
        for (int nf = 0; nf < 8; nf++)
#pragma unroll
            for (int e = 0; e < 4; e++) s[nf][e] = 0.f;
#pragma unroll
        for (int ks = 0; ks < 4; ks++) {
#pragma unroll
            for (int nf = 0; nf < 8; nf++) {
                uint32_t bkh[2], bkl[2];
                int off = (nf * 8 + r0) * ASTR + ks * 16 + c0;
                bkh[0] = *(const uint32_t*)&sKh[off];
                bkh[1] = *(const uint32_t*)&sKh[off + 8];
                bkl[0] = *(const uint32_t*)&sKl[off];
                bkl[1] = *(const uint32_t*)&sKl[off + 8];
                MMA_BF16(s[nf], qh[ks], bkh);
                MMA_BF16(s[nf], qh[ks], bkl);
                MMA_BF16(s[nf], ql[ks], bkh);
            }
        }
        __syncwarp();   // G rows are warp-private

        // ---- gather BD from G band and add ----
#pragma unroll
        for (int nf = 0; nf < 8; nf++)
#pragma unroll
            for (int e = 0; e < 4; e++) {
                int iw = r0 + ((e >> 1) << 3);               // i within warp block
                int jl = nf * 8 + c0 + (e & 1);
                s[nf][e] += sGw[iw * GBSTR + (iw - jl + 63)];
            }

        // ---- online softmax ----
        float mx0 = -1e30f, mx1 = -1e30f;
#pragma unroll
        for (int nf = 0; nf < 8; nf++) {
            mx0 = fmaxf(mx0, fmaxf(s[nf][0], s[nf][1]));
            mx1 = fmaxf(mx1, fmaxf(s[nf][2], s[nf][3]));
        }
#pragma unroll
        for (int o = 1; o <= 2; o <<= 1) {
            mx0 = fmaxf(mx0, __shfl_xor_sync(0xffffffffu, mx0, o));
            mx1 = fmaxf(mx1, __shfl_xor_sync(0xffffffffu, mx1, o));
        }
        float nm0 = fmaxf(rmax0, mx0), nm1 = fmaxf(rmax1, mx1);
        float al0 = __expf(rmax0 - nm0), al1 = __expf(rmax1 - nm1);
        rmax0 = nm0; rmax1 = nm1;
        float ls0 = 0.f, ls1 = 0.f;
#pragma unroll
        for (int nf = 0; nf < 8; nf++) {
            s[nf][0] = __expf(s[nf][0] - nm0);
            s[nf][1] = __expf(s[nf][1] - nm0);
            s[nf][2] = __expf(s[nf][2] - nm1);
            s[nf][3] = __expf(s[nf][3] - nm1);
            ls0 += s[nf][0] + s[nf][1];
            ls1 += s[nf][2] + s[nf][3];
        }
#pragma unroll
        for (int o = 1; o <= 2; o <<= 1) {
            ls0 += __shfl_xor_sync(0xffffffffu, ls0, o);
            ls1 += __shfl_xor_sync(0xffffffffu, ls1, o);
        }
        rsum0 = rsum0 * al0 + ls0;
        rsum1 = rsum1 * al1 + ls1;
#pragma unroll
        for (int nf = 0; nf < 8; nf++) {
            accO[nf][0] *= al0; accO[nf][1] *= al0;
            accO[nf][2] *= al1; accO[nf][3] *= al1;
        }

        // ---- pack P fragments (hi + residual-lo) ----
        uint32_t ph[4][4], pl[4][4];
#pragma unroll
        for (int ks = 0; ks < 4; ks++) {
            int f0 = 2 * ks, f1 = 2 * ks + 1;
            float rlo[8];
#pragma unroll
            for (int e = 0; e < 4; e++) {
                rlo[e]     = s[f0][e] - __bfloat162float(__float2bfloat16_rn(s[f0][e]));
                rlo[4 + e] = s[f1][e] - __bfloat162float(__float2bfloat16_rn(s[f1][e]));
            }
            ph[ks][0] = pack_bf2(s[f0][0], s[f0][1]);
            ph[ks][1] = pack_bf2(s[f0][2], s[f0][3]);
            ph[ks][2] = pack_bf2(s[f1][0], s[f1][1]);
            ph[ks][3] = pack_bf2(s[f1][2], s[f1][3]);
            pl[ks][0] = pack_bf2(rlo[0], rlo[1]);
            pl[ks][1] = pack_bf2(rlo[2], rlo[3]);
            pl[ks][2] = pack_bf2(rlo[4], rlo[5]);
            pl[ks][3] = pack_bf2(rlo[6], rlo[7]);
        }

        // ---- O += P * V ----
#pragma unroll
        for (int ks = 0; ks < 4; ks++) {
#pragma unroll
            for (int nf = 0; nf < 8; nf++) {
                uint32_t bvh[2], bvl[2];
                int off = (nf * 8 + r0) * ASTR + ks * 16 + c0;
                bvh[0] = *(const uint32_t*)&sVh[off];
                bvh[1] = *(const uint32_t*)&sVh[off + 8];
                bvl[0] = *(const uint32_t*)&sVl[off];
                bvl[1] = *(const uint32_t*)&sVl[off + 8];
                MMA_BF16(accO[nf], ph[ks], bvh);
                MMA_BF16(accO[nf], ph[ks], bvl);
                MMA_BF16(accO[nf], pl[ks], bvh);
            }
        }
    }

    // ---- epilogue: O / rowsum, split to bf16 hi/lo ----
    float inv0 = 1.0f / rsum0, inv1 = 1.0f / rsum1;
#pragma unroll
    for (int nf = 0; nf < 8; nf++)
#pragma unroll
        for (int e = 0; e < 4; e++) {
            int i = i0 + w * 16 + r0 + ((e >> 1) << 3);
            int d = nf * 8 + c0 + (e & 1);
            float v = accO[nf][e] * ((e < 2) ? inv0 : inv1);
            __nv_bfloat16 vh, vl;
            split_bf(v, vh, vl);
            size_t idx = ((size_t)(b * SEQ + i)) * D_MODEL + h * DK + d;
            g_oh[idx] = vh; g_ol[idx] = vl;
        }
}

// ---------------------------------------------------------------------------
extern "C" void kernel_launch(void* const* d_in, const int* in_sizes, int n_in,
                              void* d_out, int out_size)
{
    const float* x  = (const float*)d_in[0];
    const float* Wq = (const float*)d_in[1];
    const float* bq = (const float*)d_in[2];
    const float* Wk = (const float*)d_in[3];
    const float* bk = (const float*)d_in[4];
    const float* Wv = (const float*)d_in[5];
    const float* bv = (const float*)d_in[6];
    const float* Wo = (const float*)d_in[7];
    const float* bo = (const float*)d_in[8];
    const float* Er = (const float*)d_in[9];
    float* out = (float*)d_out;

    cudaFuncSetAttribute(gemm_bf16_kernel,
                         cudaFuncAttributeMaxDynamicSharedMemorySize, GEMM_DYN_SMEM);
    cudaFuncSetAttribute(attn_mma_kernel,
                         cudaFuncAttributeMaxDynamicSharedMemorySize, ATTN_SMEM);

    __nv_bfloat16 *xh, *xl, *wh, *wl, *oh, *ol;
    cudaGetSymbolAddress((void**)&xh, g_xh);
    cudaGetSymbolAddress((void**)&xl, g_xl);
    cudaGetSymbolAddress((void**)&wh, g_wh);
    cudaGetSymbolAddress((void**)&wl, g_wl);
    cudaGetSymbolAddress((void**)&oh, g_oh);
    cudaGetSymbolAddress((void**)&ol, g_ol);

    // 0) split x, weights, Er into bf16 hi/lo
    {
        int total = (MTOT * D_MODEL + 4 * D_MODEL * D_MODEL + ELEN * DK) / 4;
        convert_xw_kernel<<<(total + 255) / 256, 256>>>(x, Wq, Wk, Wv, Wo, Er);
    }
    // 1) fused QKV projection -> split-bf16 Q/K (head-major) + V^T
    {
        dim3 grid(3072 / 128, MTOT / 128);
        gemm_bf16_kernel<<<grid, 256, GEMM_DYN_SMEM>>>(
            xh, xl, wh, wl, bq, bk, bv, nullptr, 0);
    }
    // 2) MMA attention -> split-bf16 O
    {
        dim3 grid(SEQ / 64, BHT);            // 16 x 32
        attn_mma_kernel<<<grid, 128, ATTN_SMEM>>>();
    }
    // 3) output projection -> out
    {
        dim3 grid(D_MODEL / 128, MTOT / 128);
        gemm_bf16_kernel<<<grid, 256, GEMM_DYN_SMEM>>>(
            oh, ol, wh + (size_t)3 * D_MODEL * D_MODEL, wl + (size_t)3 * D_MODEL * D_MODEL,
            bo, bo, bo, out, 1);
    }
}

// round 6
// speedup vs baseline: 1.3898x; 1.3898x over previous
#include <cuda_runtime.h>
#include <cuda_bf16.h>
#include <math.h>
#include <stdint.h>

#define D_MODEL 1024
#define NH      16
#define DK      64
#define BATCH   2
#define SEQ     1024
#define BHT     (BATCH*NH)          // 32
#define MTOT    (BATCH*SEQ)         // 2048
#define ELEN    (2*SEQ-1)           // 2047

// ---------------- scratch (device globals; no allocation allowed) ----------
__device__ __nv_bfloat16 g_xh[MTOT*D_MODEL];
__device__ __nv_bfloat16 g_xl[MTOT*D_MODEL];
__device__ __nv_bfloat16 g_wh[4*D_MODEL*D_MODEL];  // Wq|Wk|Wv|Wo stacked rows
__device__ __nv_bfloat16 g_wl[4*D_MODEL*D_MODEL];
__device__ __nv_bfloat16 g_oh[MTOT*D_MODEL];
__device__ __nv_bfloat16 g_ol[MTOT*D_MODEL];

__device__ __nv_bfloat16 g_Qh[BHT*SEQ*DK];   // [bh][s][d], pre-scaled 1/8
__device__ __nv_bfloat16 g_Ql[BHT*SEQ*DK];
__device__ __nv_bfloat16 g_Kh[BHT*SEQ*DK];
__device__ __nv_bfloat16 g_Kl[BHT*SEQ*DK];
__device__ __nv_bfloat16 g_Vth[BHT*DK*SEQ];  // [bh][d][s]  (transposed)
__device__ __nv_bfloat16 g_Vtl[BHT*DK*SEQ];
__device__ __nv_bfloat16 g_Eh[ELEN*DK];
__device__ __nv_bfloat16 g_El[ELEN*DK];

// ---------------- helpers ---------------------------------------------------
__device__ __forceinline__ uint32_t smem_u32(const void* p) {
    uint32_t a;
    asm("{ .reg .u64 t; cvta.to.shared.u64 t, %1; cvt.u32.u64 %0, t; }"
        : "=r"(a) : "l"(p));
    return a;
}

#define CPA16(dst_u32, src_ptr) \
    asm volatile("cp.async.ca.shared.global [%0], [%1], 16;" \
                 :: "r"(dst_u32), "l"(src_ptr) : "memory")
#define CP_COMMIT() asm volatile("cp.async.commit_group;" ::: "memory")
#define CP_WAIT0()  asm volatile("cp.async.wait_group 0;" ::: "memory")
#define CP_WAIT1()  asm volatile("cp.async.wait_group 1;" ::: "memory")

#define LDMATRIX_X4(r0, r1, r2, r3, addr) \
    asm volatile("ldmatrix.sync.aligned.m8n8.x4.shared.b16 {%0,%1,%2,%3}, [%4];" \
                 : "=r"(r0), "=r"(r1), "=r"(r2), "=r"(r3) : "r"(addr))

#define MMA_BF16(c, a, b) \
    asm volatile("mma.sync.aligned.m16n8k16.row.col.f32.bf16.bf16.f32 " \
                 "{%0,%1,%2,%3}, {%4,%5,%6,%7}, {%8,%9}, {%0,%1,%2,%3};" \
                 : "+f"((c)[0]), "+f"((c)[1]), "+f"((c)[2]), "+f"((c)[3]) \
                 : "r"((a)[0]), "r"((a)[1]), "r"((a)[2]), "r"((a)[3]), \
                   "r"((b)[0]), "r"((b)[1]))

__device__ __forceinline__ uint32_t pack_bf2(float lo, float hi) {
    __nv_bfloat162 t = __floats2bfloat162_rn(lo, hi);
    return *(uint32_t*)&t;
}
__device__ __forceinline__ void split_bf(float v, __nv_bfloat16& h, __nv_bfloat16& l) {
    h = __float2bfloat16_rn(v);
    l = __float2bfloat16_rn(v - __bfloat162float(h));
}

// ---------------------------------------------------------------------------
// fp32 -> bf16 hi/lo split conversion (x, 4 weights, Er)
// ---------------------------------------------------------------------------
__global__ void convert_xw_kernel(const float* __restrict__ x,
                                  const float* __restrict__ Wq, const float* __restrict__ Wk,
                                  const float* __restrict__ Wv, const float* __restrict__ Wo,
                                  const float* __restrict__ Er)
{
    const int NX = MTOT * D_MODEL / 4;
    const int NW = D_MODEL * D_MODEL / 4;
    const int NE = ELEN * DK / 4;
    int g = blockIdx.x * blockDim.x + threadIdx.x;
    if (g >= NX + 4 * NW + NE) return;
    const float* src;
    __nv_bfloat16 *dh, *dl;
    if (g < NX) { src = x + g * 4; dh = g_xh + g * 4; dl = g_xl + g * 4; }
    else if (g < NX + 4 * NW) {
        int wi = g - NX;
        int which = wi / NW;
        int off = wi - which * NW;
        const float* W = (which == 0) ? Wq : (which == 1) ? Wk : (which == 2) ? Wv : Wo;
        src = W + off * 4;
        dh = g_wh + (size_t)which * NW * 4 + off * 4;
        dl = g_wl + (size_t)which * NW * 4 + off * 4;
    } else {
        int ei = g - NX - 4 * NW;
        src = Er + ei * 4; dh = g_Eh + ei * 4; dl = g_El + ei * 4;
    }
    float4 v = *(const float4*)src;
    __nv_bfloat16 hv[4], lv[4];
    split_bf(v.x, hv[0], lv[0]); split_bf(v.y, hv[1], lv[1]);
    split_bf(v.z, hv[2], lv[2]); split_bf(v.w, hv[3], lv[3]);
    *(uint2*)dh = *(uint2*)hv;
    *(uint2*)dl = *(uint2*)lv;
}

// ---------------------------------------------------------------------------
// Split-bf16 mma.sync GEMM (R4 version: LDG prefetch into registers).
// ---------------------------------------------------------------------------
#define HSTR 40
#define MAT_HALVES (128*HSTR)
#define BUF_HALVES (4*MAT_HALVES)
#define GEMM_DYN_SMEM (2*BUF_HALVES*2)        // 81920 B

__global__ __launch_bounds__(256, 1)
void gemm_bf16_kernel(const __nv_bfloat16* __restrict__ Ah, const __nv_bfloat16* __restrict__ Al,
                      const __nv_bfloat16* __restrict__ Bh, const __nv_bfloat16* __restrict__ Bl,
                      const float* __restrict__ bias0, const float* __restrict__ bias1,
                      const float* __restrict__ bias2,
                      float* __restrict__ Cout, int mode)
{
    extern __shared__ __nv_bfloat16 sm[];

    const int tid  = threadIdx.x;
    const int wid  = tid >> 5;
    const int lane = tid & 31;
    const int warp_m = wid >> 2;
    const int warp_n = wid & 3;
    const int m0 = blockIdx.y * 128;
    const int n0 = blockIdx.x * 128;
    const int which = n0 >> 10;
    const int n0m = n0 & 1023;
    const float* biasm = (which == 0) ? bias0 : (which == 1) ? bias1 : bias2;

    float acc[4][4][4];
#pragma unroll
    for (int f = 0; f < 4; f++)
#pragma unroll
        for (int g = 0; g < 4; g++)
#pragma unroll
            for (int e = 0; e < 4; e++) acc[f][g][e] = 0.f;

    const int lrow = tid >> 2;
    const int lk   = (tid & 3) * 8;

    {
        __nv_bfloat16* buf = sm;
#pragma unroll
        for (int i = 0; i < 2; i++) {
            int row = lrow + i * 64;
            *(uint4*)&buf[0 * MAT_HALVES + row * HSTR + lk] =
                *(const uint4*)(Ah + (size_t)(m0 + row) * 1024 + lk);
            *(uint4*)&buf[1 * MAT_HALVES + row * HSTR + lk] =
                *(const uint4*)(Al + (size_t)(m0 + row) * 1024 + lk);
            *(uint4*)&buf[2 * MAT_HALVES + row * HSTR + lk] =
                *(const uint4*)(Bh + (size_t)(n0 + row) * 1024 + lk);
            *(uint4*)&buf[3 * MAT_HALVES + row * HSTR + lk] =
                *(const uint4*)(Bl + (size_t)(n0 + row) * 1024 + lk);
        }
    }
    __syncthreads();

    const int a_r   = lane & 15;
    const int a_kof = (lane >> 4) * 8;

    for (int c = 0; c < 32; c++) {
        const int cur = c & 1;
        __nv_bfloat16* cb = sm + cur * BUF_HALVES;

        if (c < 31) {
            __nv_bfloat16* nb = sm + (1 - cur) * BUF_HALVES;
            int kg = (c + 1) * 32 + lk;
#pragma unroll
            for (int i = 0; i < 2; i++) {
                int row = lrow + i * 64;
                *(uint4*)&nb[0 * MAT_HALVES + row * HSTR + lk] =
                    *(const uint4*)(Ah + (size_t)(m0 + row) * 1024 + kg);
                *(uint4*)&nb[1 * MAT_HALVES + row * HSTR + lk] =
                    *(const uint4*)(Al + (size_t)(m0 + row) * 1024 + kg);
                *(uint4*)&nb[2 * MAT_HALVES + row * HSTR + lk] =
                    *(const uint4*)(Bh + (size_t)(n0 + row) * 1024 + kg);
                *(uint4*)&nb[3 * MAT_HALVES + row * HSTR + lk] =
                    *(const uint4*)(Bl + (size_t)(n0 + row) * 1024 + kg);
            }
        }

#pragma unroll
        for (int ks = 0; ks < 2; ks++) {
            uint32_t aH[4][4], aL[4][4], bH[4][2], bL[4][2];
#pragma unroll
            for (int f = 0; f < 4; f++) {
                int row = warp_m * 64 + f * 16 + a_r;
                uint32_t addrH = smem_u32(&cb[0 * MAT_HALVES + row * HSTR + ks * 16 + a_kof]);
                LDMATRIX_X4(aH[f][0], aH[f][1], aH[f][2], aH[f][3], addrH);
                uint32_t addrL = smem_u32(&cb[1 * MAT_HALVES + row * HSTR + ks * 16 + a_kof]);
                LDMATRIX_X4(aL[f][0], aL[f][1], aL[f][2], aL[f][3], addrL);
            }
#pragma unroll
            for (int g = 0; g < 4; g++) {
                int n = warp_n * 32 + g * 8 + (lane >> 2);
                int off = n * HSTR + ks * 16 + (lane & 3) * 2;
                bH[g][0] = *(const uint32_t*)&cb[2 * MAT_HALVES + off];
                bH[g][1] = *(const uint32_t*)&cb[2 * MAT_HALVES + off + 8];
                bL[g][0] = *(const uint32_t*)&cb[3 * MAT_HALVES + off];
                bL[g][1] = *(const uint32_t*)&cb[3 * MAT_HALVES + off + 8];
            }
#pragma unroll
            for (int f = 0; f < 4; f++)
#pragma unroll
                for (int g = 0; g < 4; g++) {
                    MMA_BF16(acc[f][g], aH[f], bH[g]);
                    MMA_BF16(acc[f][g], aH[f], bL[g]);
                    MMA_BF16(acc[f][g], aL[f], bH[g]);
                }
        }
        __syncthreads();
    }

    if (mode == 0) {
        const float scale = (which == 0) ? 0.125f : 1.0f;
#pragma unroll
        for (int f = 0; f < 4; f++) {
            int mrow0 = m0 + warp_m * 64 + f * 16 + (lane >> 2);
#pragma unroll
            for (int g = 0; g < 4; g++) {
                int ncol = n0m + warp_n * 32 + g * 8 + (lane & 3) * 2;
#pragma unroll
                for (int e = 0; e < 4; e++) {
                    int m = mrow0 + (e >> 1) * 8;
                    int nm = ncol + (e & 1);
                    int b = m >> 10, s = m & 1023;
                    int h = nm >> 6, d = nm & 63;
                    float val = (acc[f][g][e] + biasm[nm]) * scale;
                    __nv_bfloat16 vh, vl;
                    split_bf(val, vh, vl);
                    if (which == 2) {
                        size_t idx = ((size_t)(b * NH + h) * DK + d) * SEQ + s;
                        g_Vth[idx] = vh; g_Vtl[idx] = vl;
                    } else if (which == 0) {
                        size_t idx = ((size_t)(b * NH + h) * SEQ + s) * DK + d;
                        g_Qh[idx] = vh; g_Ql[idx] = vl;
                    } else {
                        size_t idx = ((size_t)(b * NH + h) * SEQ + s) * DK + d;
                        g_Kh[idx] = vh; g_Kl[idx] = vl;
                    }
                }
            }
        }
    } else {
#pragma unroll
        for (int f = 0; f < 4; f++) {
            int mrow0 = m0 + warp_m * 64 + f * 16 + (lane >> 2);
#pragma unroll
            for (int g = 0; g < 4; g++) {
                int ncol = n0 + warp_n * 32 + g * 8 + (lane & 3) * 2;
#pragma unroll
                for (int e = 0; e < 4; e++) {
                    int m = mrow0 + (e >> 1) * 8;
                    int n = ncol + (e & 1);
                    Cout[(size_t)m * D_MODEL + n] = acc[f][g][e] + biasm[n];
                }
            }
        }
    }
}

// ---------------------------------------------------------------------------
// Pipelined MMA flash-attention: 256 threads / 8 warps, 128 query rows/CTA,
// double-buffered K/V/E via cp.async.ca issued one tile ahead,
// band-limited G (10 n-frags per warp).
// ---------------------------------------------------------------------------
#define ASTR  72
#define GBSTR 84
#define ST_KH 0
#define ST_KL (64*ASTR)
#define ST_VH (2*64*ASTR)
#define ST_VL (3*64*ASTR)
#define ST_EH (4*64*ASTR)
#define ST_EL (4*64*ASTR + 192*ASTR)
#define STAGE_HALVES (4*64*ASTR + 2*192*ASTR)    // 46080 halves = 92160 B
#define G_OFF_HALVES (2*STAGE_HALVES)            // 92160 halves
#define ATTN_SMEM (G_OFF_HALVES*2 + 8*16*GBSTR*4)  // 184320 + 43008 = 227328 B

__device__ __forceinline__ void attn_issue_tile(
    uint32_t smb, int jt, int stg, int tid, int i0,
    const __nv_bfloat16* Khg, const __nv_bfloat16* Klg,
    const __nv_bfloat16* Vhg, const __nv_bfloat16* Vlg)
{
    const int j0 = jt * 64;
    const uint32_t base = smb + stg * STAGE_HALVES * 2;
    for (int t = tid; t < 512; t += 256) {
        int r = t >> 3, c8 = (t & 7) * 8;
        uint32_t doff = (r * ASTR + c8) * 2;
        CPA16(base + ST_KH * 2 + doff, Khg + (size_t)(j0 + r) * DK + c8);
        CPA16(base + ST_KL * 2 + doff, Klg + (size_t)(j0 + r) * DK + c8);
        CPA16(base + ST_VH * 2 + doff, Vhg + (size_t)r * SEQ + j0 + c8);
        CPA16(base + ST_VL * 2 + doff, Vlg + (size_t)r * SEQ + j0 + c8);
    }
    const int rbase = (SEQ - 1) + i0 - j0 - 63;
    for (int t = tid; t < 1536; t += 256) {
        int r = t >> 3, c8 = (t & 7) * 8;
        int er = rbase + r;
        er = (er > ELEN - 1) ? (ELEN - 1) : er;   // loaded rows beyond band never gathered
        uint32_t doff = (r * ASTR + c8) * 2;
        CPA16(base + ST_EH * 2 + doff, g_Eh + (size_t)er * DK + c8);
        CPA16(base + ST_EL * 2 + doff, g_El + (size_t)er * DK + c8);
    }
    CP_COMMIT();
}

__global__ __launch_bounds__(256)
void attn_mma_kernel()
{
    extern __shared__ __nv_bfloat16 smh[];
    float* sG = (float*)(smh + G_OFF_HALVES);          // 8 warps x 16 x 84 fp32
    __nv_bfloat16* sQh = (__nv_bfloat16*)sG;           // staging overlay (36864B<43008B)
    __nv_bfloat16* sQl = sQh + 128 * ASTR;

    const int tid  = threadIdx.x;
    const int lane = tid & 31;
    const int w    = tid >> 5;
    const int bh = blockIdx.y;
    const int i0 = blockIdx.x * 128;
    const int b = bh >> 4, h = bh & 15;

    const __nv_bfloat16* Qhg = g_Qh + (size_t)bh * SEQ * DK;
    const __nv_bfloat16* Qlg = g_Ql + (size_t)bh * SEQ * DK;
    const __nv_bfloat16* Khg = g_Kh + (size_t)bh * SEQ * DK;
    const __nv_bfloat16* Klg = g_Kl + (size_t)bh * SEQ * DK;
    const __nv_bfloat16* Vhg = g_Vth + (size_t)bh * DK * SEQ;
    const __nv_bfloat16* Vlg = g_Vtl + (size_t)bh * DK * SEQ;
    const uint32_t smb = smem_u32(smh);

    // stage Q once (G-area overlay), load A-fragments to registers
    for (int t = tid; t < 1024; t += 256) {
        int r = t >> 3, c8 = (t & 7) * 8;
        *(uint4*)&sQh[r * ASTR + c8] = *(const uint4*)(Qhg + (size_t)(i0 + r) * DK + c8);
        *(uint4*)&sQl[r * ASTR + c8] = *(const uint4*)(Qlg + (size_t)(i0 + r) * DK + c8);
    }
    __syncthreads();
    uint32_t qh[4][4], ql[4][4];
#pragma unroll
    for (int ks = 0; ks < 4; ks++) {
        uint32_t aH = smem_u32(&sQh[(w * 16 + (lane & 15)) * ASTR + ks * 16 + (lane >> 4) * 8]);
        LDMATRIX_X4(qh[ks][0], qh[ks][1], qh[ks][2], qh[ks][3], aH);
        uint32_t aL = smem_u32(&sQl[(w * 16 + (lane & 15)) * ASTR + ks * 16 + (lane >> 4) * 8]);
        LDMATRIX_X4(ql[ks][0], ql[ks][1], ql[ks][2], ql[ks][3], aL);
    }
    __syncthreads();   // all Q frags loaded before G area reused

    attn_issue_tile(smb, 0, 0, tid, i0, Khg, Klg, Vhg, Vlg);

    float accO[8][4];
#pragma unroll
    for (int nf = 0; nf < 8; nf++)
#pragma unroll
        for (int e = 0; e < 4; e++) accO[nf][e] = 0.f;
    float rmax0 = -1e30f, rmax1 = -1e30f, rsum0 = 0.f, rsum1 = 0.f;

    const int r0 = lane >> 2;
    const int c0 = (lane & 3) * 2;
    float* sGw = sG + w * 16 * GBSTR;

    for (int jt = 0; jt < 16; jt++) {
        if (jt < 15) {
            attn_issue_tile(smb, jt + 1, (jt + 1) & 1, tid, i0, Khg, Klg, Vhg, Vlg);
            CP_WAIT1();
        } else {
            CP_WAIT0();
        }
        __syncthreads();

        __nv_bfloat16* st = smh + (jt & 1) * STAGE_HALVES;
        __nv_bfloat16* sKh = st + ST_KH;
        __nv_bfloat16* sKl = st + ST_KL;
        __nv_bfloat16* sVh = st + ST_VH;
        __nv_bfloat16* sVl = st + ST_VL;
        __nv_bfloat16* sEh = st + ST_EH;
        __nv_bfloat16* sEl = st + ST_EL;

        // ---- G = Q * Eband^T, band-limited: nf in [2w, 2w+10) ----
        float gac[10][4];
#pragma unroll
        for (int bi = 0; bi < 10; bi++)
#pragma unroll
            for (int e = 0; e < 4; e++) gac[bi][e] = 0.f;
#pragma unroll
        for (int ks = 0; ks < 4; ks++) {
#pragma unroll
            for (int bi = 0; bi < 10; bi++) {
                int nf = 2 * w + bi;
                uint32_t beh[2], bel[2];
                int off = (nf * 8 + r0) * ASTR + ks * 16 + c0;
                beh[0] = *(const uint32_t*)&sEh[off];
                beh[1] = *(const uint32_t*)&sEh[off + 8];
                bel[0] = *(const uint32_t*)&sEl[off];
                bel[1] = *(const uint32_t*)&sEl[off + 8];
                MMA_BF16(gac[bi], qh[ks], beh);
                MMA_BF16(gac[bi], qh[ks], bel);
                MMA_BF16(gac[bi], ql[ks], beh);
            }
        }
#pragma unroll
        for (int bi = 0; bi < 10; bi++) {
            *(float2*)&sGw[r0 * GBSTR + bi * 8 + c0] = make_float2(gac[bi][0], gac[bi][1]);
            *(float2*)&sGw[(r0 + 8) * GBSTR + bi * 8 + c0] = make_float2(gac[bi][2], gac[bi][3]);
        }

        // ---- S = Q * K^T ----
        float s[8][4];
#pragma unroll
        for (int nf = 0; nf < 8; nf++)
#pragma unroll
            for (int e = 0; e < 4; e++) s[nf][e] = 0.f;
#pragma unroll
        for (int ks = 0; ks < 4; ks++) {
#pragma unroll
            for (int nf = 0; nf < 8; nf++) {
                uint32_t bkh[2], bkl[2];
                int off = (nf * 8 + r0) * ASTR + ks * 16 + c0;
                bkh[0] = *(const uint32_t*)&sKh[off];
                bkh[1] = *(const uint32_t*)&sKh[off + 8];
                bkl[0] = *(const uint32_t*)&sKl[off];
                bkl[1] = *(const uint32_t*)&sKl[off + 8];
                MMA_BF16(s[nf], qh[ks], bkh);
                MMA_BF16(s[nf], qh[ks], bkl);
                MMA_BF16(s[nf], ql[ks], bkh);
            }
        }
        __syncwarp();   // G rows are warp-private

        // ---- gather BD from G band and add ----
#pragma unroll
        for (int nf = 0; nf < 8; nf++)
#pragma unroll
            for (int e = 0; e < 4; e++) {
                int iw = r0 + ((e >> 1) << 3);
                int jl = nf * 8 + c0 + (e & 1);
                s[nf][e] += sGw[iw * GBSTR + (iw - jl + 63)];
            }

        // ---- online softmax ----
        float mx0 = -1e30f, mx1 = -1e30f;
#pragma unroll
        for (int nf = 0; nf < 8; nf++) {
            mx0 = fmaxf(mx0, fmaxf(s[nf][0], s[nf][1]));
            mx1 = fmaxf(mx1, fmaxf(s[nf][2], s[nf][3]));
        }
#pragma unroll
        for (int o = 1; o <= 2; o <<= 1) {
            mx0 = fmaxf(mx0, __shfl_xor_sync(0xffffffffu, mx0, o));
            mx1 = fmaxf(mx1, __shfl_xor_sync(0xffffffffu, mx1, o));
        }
        float nm0 = fmaxf(rmax0, mx0), nm1 = fmaxf(rmax1, mx1);
        float al0 = __expf(rmax0 - nm0), al1 = __expf(rmax1 - nm1);
        rmax0 = nm0; rmax1 = nm1;
        float ls0 = 0.f, ls1 = 0.f;
#pragma unroll
        for (int nf = 0; nf < 8; nf++) {
            s[nf][0] = __expf(s[nf][0] - nm0);
            s[nf][1] = __expf(s[nf][1] - nm0);
            s[nf][2] = __expf(s[nf][2] - nm1);
            s[nf][3] = __expf(s[nf][3] - nm1);
            ls0 += s[nf][0] + s[nf][1];
            ls1 += s[nf][2] + s[nf][3];
        }
#pragma unroll
        for (int o = 1; o <= 2; o <<= 1) {
            ls0 += __shfl_xor_sync(0xffffffffu, ls0, o);
            ls1 += __shfl_xor_sync(0xffffffffu, ls1, o);
        }
        rsum0 = rsum0 * al0 + ls0;
        rsum1 = rsum1 * al1 + ls1;
#pragma unroll
        for (int nf = 0; nf < 8; nf++) {
            accO[nf][0] *= al0; accO[nf][1] *= al0;
            accO[nf][2] *= al1; accO[nf][3] *= al1;
        }

        // ---- pack P fragments (hi + residual-lo) ----
        uint32_t ph[4][4], pl[4][4];
#pragma unroll
        for (int ks = 0; ks < 4; ks++) {
            int f0 = 2 * ks, f1 = 2 * ks + 1;
            float rlo[8];
#pragma unroll
            for (int e = 0; e < 4; e++) {
                rlo[e]     = s[f0][e] - __bfloat162float(__float2bfloat16_rn(s[f0][e]));
                rlo[4 + e] = s[f1][e] - __bfloat162float(__float2bfloat16_rn(s[f1][e]));
            }
            ph[ks][0] = pack_bf2(s[f0][0], s[f0][1]);
            ph[ks][1] = pack_bf2(s[f0][2], s[f0][3]);
            ph[ks][2] = pack_bf2(s[f1][0], s[f1][1]);
            ph[ks][3] = pack_bf2(s[f1][2], s[f1][3]);
            pl[ks][0] = pack_bf2(rlo[0], rlo[1]);
            pl[ks][1] = pack_bf2(rlo[2], rlo[3]);
            pl[ks][2] = pack_bf2(rlo[4], rlo[5]);
            pl[ks][3] = pack_bf2(rlo[6], rlo[7]);
        }

        // ---- O += P * V ----
#pragma unroll
        for (int ks = 0; ks < 4; ks++) {
#pragma unroll
            for (int nf = 0; nf < 8; nf++) {
                uint32_t bvh[2], bvl[2];
                int off = (nf * 8 + r0) * ASTR + ks * 16 + c0;
                bvh[0] = *(const uint32_t*)&sVh[off];
                bvh[1] = *(const uint32_t*)&sVh[off + 8];
                bvl[0] = *(const uint32_t*)&sVl[off];
                bvl[1] = *(const uint32_t*)&sVl[off + 8];
                MMA_BF16(accO[nf], ph[ks], bvh);
                MMA_BF16(accO[nf], ph[ks], bvl);
                MMA_BF16(accO[nf], pl[ks], bvh);
            }
        }
        __syncthreads();   // all reads of this stage done before re-issue
    }

    // ---- epilogue: O / rowsum, split to bf16 hi/lo ----
    float inv0 = 1.0f / rsum0, inv1 = 1.0f / rsum1;
#pragma unroll
    for (int nf = 0; nf < 8; nf++)
#pragma unroll
        for (int e = 0; e < 4; e++) {
            int i = i0 + w * 16 + r0 + ((e >> 1) << 3);
            int d = nf * 8 + c0 + (e & 1);
            float v = accO[nf][e] * ((e < 2) ? inv0 : inv1);
            __nv_bfloat16 vh, vl;
            split_bf(v, vh, vl);
            size_t idx = ((size_t)(b * SEQ + i)) * D_MODEL + h * DK + d;
            g_oh[idx] = vh; g_ol[idx] = vl;
        }
}

// ---------------------------------------------------------------------------
extern "C" void kernel_launch(void* const* d_in, const int* in_sizes, int n_in,
                              void* d_out, int out_size)
{
    const float* x  = (const float*)d_in[0];
    const float* Wq = (const float*)d_in[1];
    const float* bq = (const float*)d_in[2];
    const float* Wk = (const float*)d_in[3];
    const float* bk = (const float*)d_in[4];
    const float* Wv = (const float*)d_in[5];
    const float* bv = (const float*)d_in[6];
    const float* Wo = (const float*)d_in[7];
    const float* bo = (const float*)d_in[8];
    const float* Er = (const float*)d_in[9];
    float* out = (float*)d_out;

    cudaFuncSetAttribute(gemm_bf16_kernel,
                         cudaFuncAttributeMaxDynamicSharedMemorySize, GEMM_DYN_SMEM);
    cudaFuncSetAttribute(attn_mma_kernel,
                         cudaFuncAttributeMaxDynamicSharedMemorySize, ATTN_SMEM);

    __nv_bfloat16 *xh, *xl, *wh, *wl, *oh, *ol;
    cudaGetSymbolAddress((void**)&xh, g_xh);
    cudaGetSymbolAddress((void**)&xl, g_xl);
    cudaGetSymbolAddress((void**)&wh, g_wh);
    cudaGetSymbolAddress((void**)&wl, g_wl);
    cudaGetSymbolAddress((void**)&oh, g_oh);
    cudaGetSymbolAddress((void**)&ol, g_ol);

    // 0) split x, weights, Er into bf16 hi/lo
    {
        int total = (MTOT * D_MODEL + 4 * D_MODEL * D_MODEL + ELEN * DK) / 4;
        convert_xw_kernel<<<(total + 255) / 256, 256>>>(x, Wq, Wk, Wv, Wo, Er);
    }
    // 1) fused QKV projection -> split-bf16 Q/K (head-major) + V^T
    {
        dim3 grid(3072 / 128, MTOT / 128);
        gemm_bf16_kernel<<<grid, 256, GEMM_DYN_SMEM>>>(
            xh, xl, wh, wl, bq, bk, bv, nullptr, 0);
    }
    // 2) pipelined MMA attention -> split-bf16 O
    {
        dim3 grid(SEQ / 128, BHT);           // 8 x 32
        attn_mma_kernel<<<grid, 256, ATTN_SMEM>>>();
    }
    // 3) output projection -> out
    {
        dim3 grid(D_MODEL / 128, MTOT / 128);
        gemm_bf16_kernel<<<grid, 256, GEMM_DYN_SMEM>>>(
            oh, ol, wh + (size_t)3 * D_MODEL * D_MODEL, wl + (size_t)3 * D_MODEL * D_MODEL,
            bo, bo, bo, out, 1);
    }
}

// round 7
// speedup vs baseline: 1.4046x; 1.0107x over previous
#include <cuda_runtime.h>
#include <cuda_bf16.h>
#include <math.h>
#include <stdint.h>

#define D_MODEL 1024
#define NH      16
#define DK      64
#define BATCH   2
#define SEQ     1024
#define BHT     (BATCH*NH)          // 32
#define MTOT    (BATCH*SEQ)         // 2048
#define ELEN    (2*SEQ-1)           // 2047

// ---------------- scratch (device globals; no allocation allowed) ----------
__device__ __nv_bfloat16 g_xh[MTOT*D_MODEL];
__device__ __nv_bfloat16 g_xl[MTOT*D_MODEL];
__device__ __nv_bfloat16 g_wh[4*D_MODEL*D_MODEL];  // Wq|Wk|Wv|Wo stacked rows
__device__ __nv_bfloat16 g_wl[4*D_MODEL*D_MODEL];
__device__ __nv_bfloat16 g_oh[MTOT*D_MODEL];
__device__ __nv_bfloat16 g_ol[MTOT*D_MODEL];

__device__ __nv_bfloat16 g_Qh[BHT*SEQ*DK];   // [bh][s][d], pre-scaled 1/8
__device__ __nv_bfloat16 g_Ql[BHT*SEQ*DK];
__device__ __nv_bfloat16 g_Kh[BHT*SEQ*DK];
__device__ __nv_bfloat16 g_Kl[BHT*SEQ*DK];
__device__ __nv_bfloat16 g_Vth[BHT*DK*SEQ];  // [bh][d][s]  (transposed)
__device__ __nv_bfloat16 g_Vtl[BHT*DK*SEQ];
__device__ __nv_bfloat16 g_Eh[ELEN*DK];
__device__ __nv_bfloat16 g_El[ELEN*DK];

// ---------------- helpers ---------------------------------------------------
__device__ __forceinline__ uint32_t smem_u32(const void* p) {
    uint32_t a;
    asm("{ .reg .u64 t; cvta.to.shared.u64 t, %1; cvt.u32.u64 %0, t; }"
        : "=r"(a) : "l"(p));
    return a;
}

#define CPA16(dst_u32, src_ptr) \
    asm volatile("cp.async.ca.shared.global [%0], [%1], 16;" \
                 :: "r"(dst_u32), "l"(src_ptr) : "memory")
#define CP_COMMIT() asm volatile("cp.async.commit_group;" ::: "memory")
#define CP_WAIT0()  asm volatile("cp.async.wait_group 0;" ::: "memory")
#define CP_WAIT1()  asm volatile("cp.async.wait_group 1;" ::: "memory")

#define LDMATRIX_X4(r0, r1, r2, r3, addr) \
    asm volatile("ldmatrix.sync.aligned.m8n8.x4.shared.b16 {%0,%1,%2,%3}, [%4];" \
                 : "=r"(r0), "=r"(r1), "=r"(r2), "=r"(r3) : "r"(addr))

#define MMA_BF16(c, a, b) \
    asm volatile("mma.sync.aligned.m16n8k16.row.col.f32.bf16.bf16.f32 " \
                 "{%0,%1,%2,%3}, {%4,%5,%6,%7}, {%8,%9}, {%0,%1,%2,%3};" \
                 : "+f"((c)[0]), "+f"((c)[1]), "+f"((c)[2]), "+f"((c)[3]) \
                 : "r"((a)[0]), "r"((a)[1]), "r"((a)[2]), "r"((a)[3]), \
                   "r"((b)[0]), "r"((b)[1]))

// Load B-fragments for TWO n-frags (n8 each) at rows [row0, row0+16) with one
// ldmatrix.x4. Produces r[0..1] = frag for n-frag at row0, r[2..3] at row0+8.
// Lane mapping mirrors the scalar pattern: lane L -> n = row0 + sel*8 + (L&7),
// k = kcol + ((L>>3)&1)*8, sel = (L>>4)&1.
__device__ __forceinline__ void ldmB(const __nv_bfloat16* base, int stride,
                                     int row0, int kcol, int lane, uint32_t* r)
{
    int sel = (lane >> 4) & 1;
    int row = row0 + sel * 8 + (lane & 7);
    int col = kcol + ((lane >> 3) & 1) * 8;
    uint32_t a = smem_u32(base + row * stride + col);
    LDMATRIX_X4(r[0], r[1], r[2], r[3], a);
}

__device__ __forceinline__ uint32_t pack_bf2(float lo, float hi) {
    __nv_bfloat162 t = __floats2bfloat162_rn(lo, hi);
    return *(uint32_t*)&t;
}
__device__ __forceinline__ void split_bf(float v, __nv_bfloat16& h, __nv_bfloat16& l) {
    h = __float2bfloat16_rn(v);
    l = __float2bfloat16_rn(v - __bfloat162float(h));
}

// ---------------------------------------------------------------------------
// fp32 -> bf16 hi/lo split conversion (x, 4 weights, Er)
// ---------------------------------------------------------------------------
__global__ void convert_xw_kernel(const float* __restrict__ x,
                                  const float* __restrict__ Wq, const float* __restrict__ Wk,
                                  const float* __restrict__ Wv, const float* __restrict__ Wo,
                                  const float* __restrict__ Er)
{
    const int NX = MTOT * D_MODEL / 4;
    const int NW = D_MODEL * D_MODEL / 4;
    const int NE = ELEN * DK / 4;
    int g = blockIdx.x * blockDim.x + threadIdx.x;
    if (g >= NX + 4 * NW + NE) return;
    const float* src;
    __nv_bfloat16 *dh, *dl;
    if (g < NX) { src = x + g * 4; dh = g_xh + g * 4; dl = g_xl + g * 4; }
    else if (g < NX + 4 * NW) {
        int wi = g - NX;
        int which = wi / NW;
        int off = wi - which * NW;
        const float* W = (which == 0) ? Wq : (which == 1) ? Wk : (which == 2) ? Wv : Wo;
        src = W + off * 4;
        dh = g_wh + (size_t)which * NW * 4 + off * 4;
        dl = g_wl + (size_t)which * NW * 4 + off * 4;
    } else {
        int ei = g - NX - 4 * NW;
        src = Er + ei * 4; dh = g_Eh + ei * 4; dl = g_El + ei * 4;
    }
    float4 v = *(const float4*)src;
    __nv_bfloat16 hv[4], lv[4];
    split_bf(v.x, hv[0], lv[0]); split_bf(v.y, hv[1], lv[1]);
    split_bf(v.z, hv[2], lv[2]); split_bf(v.w, hv[3], lv[3]);
    *(uint2*)dh = *(uint2*)hv;
    *(uint2*)dl = *(uint2*)lv;
}

// ---------------------------------------------------------------------------
// Split-bf16 mma.sync GEMM (LDG prefetch; B-frags via ldmatrix.x4).
// ---------------------------------------------------------------------------
#define HSTR 40
#define MAT_HALVES (128*HSTR)
#define BUF_HALVES (4*MAT_HALVES)
#define GEMM_DYN_SMEM (2*BUF_HALVES*2)        // 81920 B

__global__ __launch_bounds__(256, 1)
void gemm_bf16_kernel(const __nv_bfloat16* __restrict__ Ah, const __nv_bfloat16* __restrict__ Al,
                      const __nv_bfloat16* __restrict__ Bh, const __nv_bfloat16* __restrict__ Bl,
                      const float* __restrict__ bias0, const float* __restrict__ bias1,
                      const float* __restrict__ bias2,
                      float* __restrict__ Cout, int mode)
{
    extern __shared__ __nv_bfloat16 sm[];

    const int tid  = threadIdx.x;
    const int wid  = tid >> 5;
    const int lane = tid & 31;
    const int warp_m = wid >> 2;
    const int warp_n = wid & 3;
    const int m0 = blockIdx.y * 128;
    const int n0 = blockIdx.x * 128;
    const int which = n0 >> 10;
    const int n0m = n0 & 1023;
    const float* biasm = (which == 0) ? bias0 : (which == 1) ? bias1 : bias2;

    float acc[4][4][4];
#pragma unroll
    for (int f = 0; f < 4; f++)
#pragma unroll
        for (int g = 0; g < 4; g++)
#pragma unroll
            for (int e = 0; e < 4; e++) acc[f][g][e] = 0.f;

    const int lrow = tid >> 2;
    const int lk   = (tid & 3) * 8;

    {
        __nv_bfloat16* buf = sm;
#pragma unroll
        for (int i = 0; i < 2; i++) {
            int row = lrow + i * 64;
            *(uint4*)&buf[0 * MAT_HALVES + row * HSTR + lk] =
                *(const uint4*)(Ah + (size_t)(m0 + row) * 1024 + lk);
            *(uint4*)&buf[1 * MAT_HALVES + row * HSTR + lk] =
                *(const uint4*)(Al + (size_t)(m0 + row) * 1024 + lk);
            *(uint4*)&buf[2 * MAT_HALVES + row * HSTR + lk] =
                *(const uint4*)(Bh + (size_t)(n0 + row) * 1024 + lk);
            *(uint4*)&buf[3 * MAT_HALVES + row * HSTR + lk] =
                *(const uint4*)(Bl + (size_t)(n0 + row) * 1024 + lk);
        }
    }
    __syncthreads();

    const int a_r   = lane & 15;
    const int a_kof = (lane >> 4) * 8;

    for (int c = 0; c < 32; c++) {
        const int cur = c & 1;
        __nv_bfloat16* cb = sm + cur * BUF_HALVES;

        if (c < 31) {
            __nv_bfloat16* nb = sm + (1 - cur) * BUF_HALVES;
            int kg = (c + 1) * 32 + lk;
#pragma unroll
            for (int i = 0; i < 2; i++) {
                int row = lrow + i * 64;
                *(uint4*)&nb[0 * MAT_HALVES + row * HSTR + lk] =
                    *(const uint4*)(Ah + (size_t)(m0 + row) * 1024 + kg);
                *(uint4*)&nb[1 * MAT_HALVES + row * HSTR + lk] =
                    *(const uint4*)(Al + (size_t)(m0 + row) * 1024 + kg);
                *(uint4*)&nb[2 * MAT_HALVES + row * HSTR + lk] =
                    *(const uint4*)(Bh + (size_t)(n0 + row) * 1024 + kg);
                *(uint4*)&nb[3 * MAT_HALVES + row * HSTR + lk] =
                    *(const uint4*)(Bl + (size_t)(n0 + row) * 1024 + kg);
            }
        }

#pragma unroll
        for (int ks = 0; ks < 2; ks++) {
            uint32_t aH[4][4], aL[4][4], bH[2][4], bL[2][4];
#pragma unroll
            for (int f = 0; f < 4; f++) {
                int row = warp_m * 64 + f * 16 + a_r;
                uint32_t addrH = smem_u32(&cb[0 * MAT_HALVES + row * HSTR + ks * 16 + a_kof]);
                LDMATRIX_X4(aH[f][0], aH[f][1], aH[f][2], aH[f][3], addrH);
                uint32_t addrL = smem_u32(&cb[1 * MAT_HALVES + row * HSTR + ks * 16 + a_kof]);
                LDMATRIX_X4(aL[f][0], aL[f][1], aL[f][2], aL[f][3], addrL);
            }
            ldmB(&cb[2 * MAT_HALVES], HSTR, warp_n * 32 +  0, ks * 16, lane, bH[0]);
            ldmB(&cb[2 * MAT_HALVES], HSTR, warp_n * 32 + 16, ks * 16, lane, bH[1]);
            ldmB(&cb[3 * MAT_HALVES], HSTR, warp_n * 32 +  0, ks * 16, lane, bL[0]);
            ldmB(&cb[3 * MAT_HALVES], HSTR, warp_n * 32 + 16, ks * 16, lane, bL[1]);
#pragma unroll
            for (int f = 0; f < 4; f++)
#pragma unroll
                for (int g = 0; g < 4; g++) {
                    const uint32_t* ph = &bH[g >> 1][(g & 1) * 2];
                    const uint32_t* pls = &bL[g >> 1][(g & 1) * 2];
                    MMA_BF16(acc[f][g], aH[f], ph);
                    MMA_BF16(acc[f][g], aH[f], pls);
                    MMA_BF16(acc[f][g], aL[f], ph);
                }
        }
        __syncthreads();
    }

    if (mode == 0) {
        const float scale = (which == 0) ? 0.125f : 1.0f;
#pragma unroll
        for (int f = 0; f < 4; f++) {
            int mrow0 = m0 + warp_m * 64 + f * 16 + (lane >> 2);
#pragma unroll
            for (int g = 0; g < 4; g++) {
                int ncol = n0m + warp_n * 32 + g * 8 + (lane & 3) * 2;
#pragma unroll
                for (int e = 0; e < 4; e++) {
                    int m = mrow0 + (e >> 1) * 8;
                    int nm = ncol + (e & 1);
                    int b = m >> 10, s = m & 1023;
                    int h = nm >> 6, d = nm & 63;
                    float val = (acc[f][g][e] + biasm[nm]) * scale;
                    __nv_bfloat16 vh, vl;
                    split_bf(val, vh, vl);
                    if (which == 2) {
                        size_t idx = ((size_t)(b * NH + h) * DK + d) * SEQ + s;
                        g_Vth[idx] = vh; g_Vtl[idx] = vl;
                    } else if (which == 0) {
                        size_t idx = ((size_t)(b * NH + h) * SEQ + s) * DK + d;
                        g_Qh[idx] = vh; g_Ql[idx] = vl;
                    } else {
                        size_t idx = ((size_t)(b * NH + h) * SEQ + s) * DK + d;
                        g_Kh[idx] = vh; g_Kl[idx] = vl;
                    }
                }
            }
        }
    } else {
#pragma unroll
        for (int f = 0; f < 4; f++) {
            int mrow0 = m0 + warp_m * 64 + f * 16 + (lane >> 2);
#pragma unroll
            for (int g = 0; g < 4; g++) {
                int ncol = n0 + warp_n * 32 + g * 8 + (lane & 3) * 2;
#pragma unroll
                for (int e = 0; e < 4; e++) {
                    int m = mrow0 + (e >> 1) * 8;
                    int n = ncol + (e & 1);
                    Cout[(size_t)m * D_MODEL + n] = acc[f][g][e] + biasm[n];
                }
            }
        }
    }
}

// ---------------------------------------------------------------------------
// Pipelined MMA flash-attention (R6 structure; frag loads via ldmatrix.x4).
// ---------------------------------------------------------------------------
#define ASTR  72
#define GBSTR 84
#define ST_KH 0
#define ST_KL (64*ASTR)
#define ST_VH (2*64*ASTR)
#define ST_VL (3*64*ASTR)
#define ST_EH (4*64*ASTR)
#define ST_EL (4*64*ASTR + 192*ASTR)
#define STAGE_HALVES (4*64*ASTR + 2*192*ASTR)    // 46080 halves = 92160 B
#define G_OFF_HALVES (2*STAGE_HALVES)            // 92160 halves
#define ATTN_SMEM (G_OFF_HALVES*2 + 8*16*GBSTR*4)  // 227328 B

__device__ __forceinline__ void attn_issue_tile(
    uint32_t smb, int jt, int stg, int tid, int i0,
    const __nv_bfloat16* Khg, const __nv_bfloat16* Klg,
    const __nv_bfloat16* Vhg, const __nv_bfloat16* Vlg)
{
    const int j0 = jt * 64;
    const uint32_t base = smb + stg * STAGE_HALVES * 2;
    for (int t = tid; t < 512; t += 256) {
        int r = t >> 3, c8 = (t & 7) * 8;
        uint32_t doff = (r * ASTR + c8) * 2;
        CPA16(base + ST_KH * 2 + doff, Khg + (size_t)(j0 + r) * DK + c8);
        CPA16(base + ST_KL * 2 + doff, Klg + (size_t)(j0 + r) * DK + c8);
        CPA16(base + ST_VH * 2 + doff, Vhg + (size_t)r * SEQ + j0 + c8);
        CPA16(base + ST_VL * 2 + doff, Vlg + (size_t)r * SEQ + j0 + c8);
    }
    const int rbase = (SEQ - 1) + i0 - j0 - 63;
    for (int t = tid; t < 1536; t += 256) {
        int r = t >> 3, c8 = (t & 7) * 8;
        int er = rbase + r;
        er = (er > ELEN - 1) ? (ELEN - 1) : er;
        uint32_t doff = (r * ASTR + c8) * 2;
        CPA16(base + ST_EH * 2 + doff, g_Eh + (size_t)er * DK + c8);
        CPA16(base + ST_EL * 2 + doff, g_El + (size_t)er * DK + c8);
    }
    CP_COMMIT();
}

__global__ __launch_bounds__(256)
void attn_mma_kernel()
{
    extern __shared__ __nv_bfloat16 smh[];
    float* sG = (float*)(smh + G_OFF_HALVES);
    __nv_bfloat16* sQh = (__nv_bfloat16*)sG;
    __nv_bfloat16* sQl = sQh + 128 * ASTR;

    const int tid  = threadIdx.x;
    const int lane = tid & 31;
    const int w    = tid >> 5;
    const int bh = blockIdx.y;
    const int i0 = blockIdx.x * 128;
    const int b = bh >> 4, h = bh & 15;

    const __nv_bfloat16* Qhg = g_Qh + (size_t)bh * SEQ * DK;
    const __nv_bfloat16* Qlg = g_Ql + (size_t)bh * SEQ * DK;
    const __nv_bfloat16* Khg = g_Kh + (size_t)bh * SEQ * DK;
    const __nv_bfloat16* Klg = g_Kl + (size_t)bh * SEQ * DK;
    const __nv_bfloat16* Vhg = g_Vth + (size_t)bh * DK * SEQ;
    const __nv_bfloat16* Vlg = g_Vtl + (size_t)bh * DK * SEQ;
    const uint32_t smb = smem_u32(smh);

    for (int t = tid; t < 1024; t += 256) {
        int r = t >> 3, c8 = (t & 7) * 8;
        *(uint4*)&sQh[r * ASTR + c8] = *(const uint4*)(Qhg + (size_t)(i0 + r) * DK + c8);
        *(uint4*)&sQl[r * ASTR + c8] = *(const uint4*)(Qlg + (size_t)(i0 + r) * DK + c8);
    }
    __syncthreads();
    uint32_t qh[4][4], ql[4][4];
#pragma unroll
    for (int ks = 0; ks < 4; ks++) {
        uint32_t aH = smem_u32(&sQh[(w * 16 + (lane & 15)) * ASTR + ks * 16 + (lane >> 4) * 8]);
        LDMATRIX_X4(qh[ks][0], qh[ks][1], qh[ks][2], qh[ks][3], aH);
        uint32_t aL = smem_u32(&sQl[(w * 16 + (lane & 15)) * ASTR + ks * 16 + (lane >> 4) * 8]);
        LDMATRIX_X4(ql[ks][0], ql[ks][1], ql[ks][2], ql[ks][3], aL);
    }
    __syncthreads();

    attn_issue_tile(smb, 0, 0, tid, i0, Khg, Klg, Vhg, Vlg);

    float accO[8][4];
#pragma unroll
    for (int nf = 0; nf < 8; nf++)
#pragma unroll
        for (int e = 0; e < 4; e++) accO[nf][e] = 0.f;
    float rmax0 = -1e30f, rmax1 = -1e30f, rsum0 = 0.f, rsum1 = 0.f;

    const int r0 = lane >> 2;
    const int c0 = (lane & 3) * 2;
    float* sGw = sG + w * 16 * GBSTR;

    for (int jt = 0; jt < 16; jt++) {
        if (jt < 15) {
            attn_issue_tile(smb, jt + 1, (jt + 1) & 1, tid, i0, Khg, Klg, Vhg, Vlg);
            CP_WAIT1();
        } else {
            CP_WAIT0();
        }
        __syncthreads();

        __nv_bfloat16* st = smh + (jt & 1) * STAGE_HALVES;
        __nv_bfloat16* sKh = st + ST_KH;
        __nv_bfloat16* sKl = st + ST_KL;
        __nv_bfloat16* sVh = st + ST_VH;
        __nv_bfloat16* sVl = st + ST_VL;
        __nv_bfloat16* sEh = st + ST_EH;
        __nv_bfloat16* sEl = st + ST_EL;

        // ---- G = Q * Eband^T, band-limited: nf in [2w, 2w+10) ----
        float gac[10][4];
#pragma unroll
        for (int bi = 0; bi < 10; bi++)
#pragma unroll
            for (int e = 0; e < 4; e++) gac[bi][e] = 0.f;
#pragma unroll
        for (int ks = 0; ks < 4; ks++) {
#pragma unroll
            for (int bp = 0; bp < 5; bp++) {
                uint32_t eh4[4], el4[4];
                int row0 = (2 * w + 2 * bp) * 8;
                ldmB(sEh, ASTR, row0, ks * 16, lane, eh4);
                ldmB(sEl, ASTR, row0, ks * 16, lane, el4);
                MMA_BF16(gac[2 * bp], qh[ks], eh4);
                MMA_BF16(gac[2 * bp], qh[ks], el4);
                MMA_BF16(gac[2 * bp], ql[ks], eh4);
                MMA_BF16(gac[2 * bp + 1], qh[ks], eh4 + 2);
                MMA_BF16(gac[2 * bp + 1], qh[ks], el4 + 2);
                MMA_BF16(gac[2 * bp + 1], ql[ks], eh4 + 2);
            }
        }
#pragma unroll
        for (int bi = 0; bi < 10; bi++) {
            *(float2*)&sGw[r0 * GBSTR + bi * 8 + c0] = make_float2(gac[bi][0], gac[bi][1]);
            *(float2*)&sGw[(r0 + 8) * GBSTR + bi * 8 + c0] = make_float2(gac[bi][2], gac[bi][3]);
        }

        // ---- S = Q * K^T ----
        float s[8][4];
#pragma unroll
        for (int nf = 0; nf < 8; nf++)
#pragma unroll
            for (int e = 0; e < 4; e++) s[nf][e] = 0.f;
#pragma unroll
        for (int ks = 0; ks < 4; ks++) {
#pragma unroll
            for (int gp = 0; gp < 4; gp++) {
                uint32_t kh4[4], kl4[4];
                ldmB(sKh, ASTR, gp * 16, ks * 16, lane, kh4);
                ldmB(sKl, ASTR, gp * 16, ks * 16, lane, kl4);
                MMA_BF16(s[2 * gp], qh[ks], kh4);
                MMA_BF16(s[2 * gp], qh[ks], kl4);
                MMA_BF16(s[2 * gp], ql[ks], kh4);
                MMA_BF16(s[2 * gp + 1], qh[ks], kh4 + 2);
                MMA_BF16(s[2 * gp + 1], qh[ks], kl4 + 2);
                MMA_BF16(s[2 * gp + 1], ql[ks], kh4 + 2);
            }
        }
        __syncwarp();

        // ---- gather BD from G band and add ----
#pragma unroll
        for (int nf = 0; nf < 8; nf++)
#pragma unroll
            for (int e = 0; e < 4; e++) {
                int iw = r0 + ((e >> 1) << 3);
                int jl = nf * 8 + c0 + (e & 1);
                s[nf][e] += sGw[iw * GBSTR + (iw - jl + 63)];
            }

        // ---- online softmax ----
        float mx0 = -1e30f, mx1 = -1e30f;
#pragma unroll
        for (int nf = 0; nf < 8; nf++) {
            mx0 = fmaxf(mx0, fmaxf(s[nf][0], s[nf][1]));
            mx1 = fmaxf(mx1, fmaxf(s[nf][2], s[nf][3]));
        }
#pragma unroll
        for (int o = 1; o <= 2; o <<= 1) {
            mx0 = fmaxf(mx0, __shfl_xor_sync(0xffffffffu, mx0, o));
            mx1 = fmaxf(mx1, __shfl_xor_sync(0xffffffffu, mx1, o));
        }
        float nm0 = fmaxf(rmax0, mx0), nm1 = fmaxf(rmax1, mx1);
        float al0 = __expf(rmax0 - nm0), al1 = __expf(rmax1 - nm1);
        rmax0 = nm0; rmax1 = nm1;
        float ls0 = 0.f, ls1 = 0.f;
#pragma unroll
        for (int nf = 0; nf < 8; nf++) {
            s[nf][0] = __expf(s[nf][0] - nm0);
            s[nf][1] = __expf(s[nf][1] - nm0);
            s[nf][2] = __expf(s[nf][2] - nm1);
            s[nf][3] = __expf(s[nf][3] - nm1);
            ls0 += s[nf][0] + s[nf][1];
            ls1 += s[nf][2] + s[nf][3];
        }
#pragma unroll
        for (int o = 1; o <= 2; o <<= 1) {
            ls0 += __shfl_xor_sync(0xffffffffu, ls0, o);
            ls1 += __shfl_xor_sync(0xffffffffu, ls1, o);
        }
        rsum0 = rsum0 * al0 + ls0;
        rsum1 = rsum1 * al1 + ls1;
#pragma unroll
        for (int nf = 0; nf < 8; nf++) {
            accO[nf][0] *= al0; accO[nf][1] *= al0;
            accO[nf][2] *= al1; accO[nf][3] *= al1;
        }

        // ---- pack P fragments (hi + residual-lo) ----
        uint32_t ph[4][4], pl[4][4];
#pragma unroll
        for (int ks = 0; ks < 4; ks++) {
            int f0 = 2 * ks, f1 = 2 * ks + 1;
            float rlo[8];
#pragma unroll
            for (int e = 0; e < 4; e++) {
                rlo[e]     = s[f0][e] - __bfloat162float(__float2bfloat16_rn(s[f0][e]));
                rlo[4 + e] = s[f1][e] - __bfloat162float(__float2bfloat16_rn(s[f1][e]));
            }
            ph[ks][0] = pack_bf2(s[f0][0], s[f0][1]);
            ph[ks][1] = pack_bf2(s[f0][2], s[f0][3]);
            ph[ks][2] = pack_bf2(s[f1][0], s[f1][1]);
            ph[ks][3] = pack_bf2(s[f1][2], s[f1][3]);
            pl[ks][0] = pack_bf2(rlo[0], rlo[1]);
            pl[ks][1] = pack_bf2(rlo[2], rlo[3]);
            pl[ks][2] = pack_bf2(rlo[4], rlo[5]);
            pl[ks][3] = pack_bf2(rlo[6], rlo[7]);
        }

        // ---- O += P * V ----
#pragma unroll
        for (int ks = 0; ks < 4; ks++) {
#pragma unroll
            for (int gp = 0; gp < 4; gp++) {
                uint32_t vh4[4], vl4[4];
                ldmB(sVh, ASTR, gp * 16, ks * 16, lane, vh4);
                ldmB(sVl, ASTR, gp * 16, ks * 16, lane, vl4);
                MMA_BF16(accO[2 * gp], ph[ks], vh4);
                MMA_BF16(accO[2 * gp], ph[ks], vl4);
                MMA_BF16(accO[2 * gp], pl[ks], vh4);
                MMA_BF16(accO[2 * gp + 1], ph[ks], vh4 + 2);
                MMA_BF16(accO[2 * gp + 1], ph[ks], vl4 + 2);
                MMA_BF16(accO[2 * gp + 1], pl[ks], vh4 + 2);
            }
        }
        __syncthreads();
    }

    // ---- epilogue ----
    float inv0 = 1.0f / rsum0, inv1 = 1.0f / rsum1;
#pragma unroll
    for (int nf = 0; nf < 8; nf++)
#pragma unroll
        for (int e = 0; e < 4; e++) {
            int i = i0 + w * 16 + r0 + ((e >> 1) << 3);
            int d = nf * 8 + c0 + (e & 1);
            float v = accO[nf][e] * ((e < 2) ? inv0 : inv1);
            __nv_bfloat16 vh, vl;
            split_bf(v, vh, vl);
            size_t idx = ((size_t)(b * SEQ + i)) * D_MODEL + h * DK + d;
            g_oh[idx] = vh; g_ol[idx] = vl;
        }
}

// ---------------------------------------------------------------------------
extern "C" void kernel_launch(void* const* d_in, const int* in_sizes, int n_in,
                              void* d_out, int out_size)
{
    const float* x  = (const float*)d_in[0];
    const float* Wq = (const float*)d_in[1];
    const float* bq = (const float*)d_in[2];
    const float* Wk = (const float*)d_in[3];
    const float* bk = (const float*)d_in[4];
    const float* Wv = (const float*)d_in[5];
    const float* bv = (const float*)d_in[6];
    const float* Wo = (const float*)d_in[7];
    const float* bo = (const float*)d_in[8];
    const float* Er = (const float*)d_in[9];
    float* out = (float*)d_out;

    cudaFuncSetAttribute(gemm_bf16_kernel,
                         cudaFuncAttributeMaxDynamicSharedMemorySize, GEMM_DYN_SMEM);
    cudaFuncSetAttribute(attn_mma_kernel,
                         cudaFuncAttributeMaxDynamicSharedMemorySize, ATTN_SMEM);

    __nv_bfloat16 *xh, *xl, *wh, *wl, *oh, *ol;
    cudaGetSymbolAddress((void**)&xh, g_xh);
    cudaGetSymbolAddress((void**)&xl, g_xl);
    cudaGetSymbolAddress((void**)&wh, g_wh);
    cudaGetSymbolAddress((void**)&wl, g_wl);
    cudaGetSymbolAddress((void**)&oh, g_oh);
    cudaGetSymbolAddress((void**)&ol, g_ol);

    // 0) split x, weights, Er into bf16 hi/lo
    {
        int total = (MTOT * D_MODEL + 4 * D_MODEL * D_MODEL + ELEN * DK) / 4;
        convert_xw_kernel<<<(total + 255) / 256, 256>>>(x, Wq, Wk, Wv, Wo, Er);
    }
    // 1) fused QKV projection -> split-bf16 Q/K (head-major) + V^T
    {
        dim3 grid(3072 / 128, MTOT / 128);
        gemm_bf16_kernel<<<grid, 256, GEMM_DYN_SMEM>>>(
            xh, xl, wh, wl, bq, bk, bv, nullptr, 0);
    }
    // 2) pipelined MMA attention -> split-bf16 O
    {
        dim3 grid(SEQ / 128, BHT);           // 8 x 32
        attn_mma_kernel<<<grid, 256, ATTN_SMEM>>>();
    }
    // 3) output projection -> out
    {
        dim3 grid(D_MODEL / 128, MTOT / 128);
        gemm_bf16_kernel<<<grid, 256, GEMM_DYN_SMEM>>>(
            oh, ol, wh + (size_t)3 * D_MODEL * D_MODEL, wl + (size_t)3 * D_MODEL * D_MODEL,
            bo, bo, bo, out, 1);
    }
}

// round 8
// speedup vs baseline: 1.5856x; 1.1288x over previous
#include <cuda_runtime.h>
#include <cuda_bf16.h>
#include <math.h>
#include <stdint.h>

#define D_MODEL 1024
#define NH      16
#define DK      64
#define BATCH   2
#define SEQ     1024
#define BHT     (BATCH*NH)          // 32
#define MTOT    (BATCH*SEQ)         // 2048
#define ELEN    (2*SEQ-1)           // 2047

// ---------------- scratch (device globals; no allocation allowed) ----------
__device__ __nv_bfloat16 g_xh[MTOT*D_MODEL];
__device__ __nv_bfloat16 g_xl[MTOT*D_MODEL];
__device__ __nv_bfloat16 g_wh[4*D_MODEL*D_MODEL];  // Wq|Wk|Wv|Wo stacked rows
__device__ __nv_bfloat16 g_wl[4*D_MODEL*D_MODEL];
__device__ __nv_bfloat16 g_oh[MTOT*D_MODEL];
__device__ __nv_bfloat16 g_ol[MTOT*D_MODEL];

__device__ __nv_bfloat16 g_Qh[BHT*SEQ*DK];   // [bh][s][d], pre-scaled 1/8
__device__ __nv_bfloat16 g_Ql[BHT*SEQ*DK];
__device__ __nv_bfloat16 g_Kh[BHT*SEQ*DK];
__device__ __nv_bfloat16 g_Kl[BHT*SEQ*DK];
__device__ __nv_bfloat16 g_Vth[BHT*DK*SEQ];  // [bh][d][s]  (transposed)
__device__ __nv_bfloat16 g_Vtl[BHT*DK*SEQ];
__device__ __nv_bfloat16 g_Eh[ELEN*DK];
__device__ __nv_bfloat16 g_El[ELEN*DK];

// ---------------- helpers ---------------------------------------------------
__device__ __forceinline__ uint32_t smem_u32(const void* p) {
    uint32_t a;
    asm("{ .reg .u64 t; cvta.to.shared.u64 t, %1; cvt.u32.u64 %0, t; }"
        : "=r"(a) : "l"(p));
    return a;
}

#define CPA16(dst_u32, src_ptr) \
    asm volatile("cp.async.ca.shared.global [%0], [%1], 16;" \
                 :: "r"(dst_u32), "l"(src_ptr) : "memory")
#define CP_COMMIT() asm volatile("cp.async.commit_group;" ::: "memory")
#define CP_WAIT0()  asm volatile("cp.async.wait_group 0;" ::: "memory")
#define CP_WAIT1()  asm volatile("cp.async.wait_group 1;" ::: "memory")

#define LDMATRIX_X4(r0, r1, r2, r3, addr) \
    asm volatile("ldmatrix.sync.aligned.m8n8.x4.shared.b16 {%0,%1,%2,%3}, [%4];" \
                 : "=r"(r0), "=r"(r1), "=r"(r2), "=r"(r3) : "r"(addr))

#define MMA_BF16(c, a, b) \
    asm volatile("mma.sync.aligned.m16n8k16.row.col.f32.bf16.bf16.f32 " \
                 "{%0,%1,%2,%3}, {%4,%5,%6,%7}, {%8,%9}, {%0,%1,%2,%3};" \
                 : "+f"((c)[0]), "+f"((c)[1]), "+f"((c)[2]), "+f"((c)[3]) \
                 : "r"((a)[0]), "r"((a)[1]), "r"((a)[2]), "r"((a)[3]), \
                   "r"((b)[0]), "r"((b)[1]))

// Load B-fragments for TWO n-frags with one ldmatrix.x4.
__device__ __forceinline__ void ldmB(const __nv_bfloat16* base, int stride,
                                     int row0, int kcol, int lane, uint32_t* r)
{
    int sel = (lane >> 4) & 1;
    int row = row0 + sel * 8 + (lane & 7);
    int col = kcol + ((lane >> 3) & 1) * 8;
    uint32_t a = smem_u32(base + row * stride + col);
    LDMATRIX_X4(r[0], r[1], r[2], r[3], a);
}

__device__ __forceinline__ uint32_t pack_bf2(float lo, float hi) {
    __nv_bfloat162 t = __floats2bfloat162_rn(lo, hi);
    return *(uint32_t*)&t;
}
__device__ __forceinline__ void split_bf(float v, __nv_bfloat16& h, __nv_bfloat16& l) {
    h = __float2bfloat16_rn(v);
    l = __float2bfloat16_rn(v - __bfloat162float(h));
}

// ---------------------------------------------------------------------------
// fp32 -> bf16 hi/lo split conversion (x, 4 weights, Er)
// ---------------------------------------------------------------------------
__global__ void convert_xw_kernel(const float* __restrict__ x,
                                  const float* __restrict__ Wq, const float* __restrict__ Wk,
                                  const float* __restrict__ Wv, const float* __restrict__ Wo,
                                  const float* __restrict__ Er)
{
    const int NX = MTOT * D_MODEL / 4;
    const int NW = D_MODEL * D_MODEL / 4;
    const int NE = ELEN * DK / 4;
    int g = blockIdx.x * blockDim.x + threadIdx.x;
    if (g >= NX + 4 * NW + NE) return;
    const float* src;
    __nv_bfloat16 *dh, *dl;
    if (g < NX) { src = x + g * 4; dh = g_xh + g * 4; dl = g_xl + g * 4; }
    else if (g < NX + 4 * NW) {
        int wi = g - NX;
        int which = wi / NW;
        int off = wi - which * NW;
        const float* W = (which == 0) ? Wq : (which == 1) ? Wk : (which == 2) ? Wv : Wo;
        src = W + off * 4;
        dh = g_wh + (size_t)which * NW * 4 + off * 4;
        dl = g_wl + (size_t)which * NW * 4 + off * 4;
    } else {
        int ei = g - NX - 4 * NW;
        src = Er + ei * 4; dh = g_Eh + ei * 4; dl = g_El + ei * 4;
    }
    float4 v = *(const float4*)src;
    __nv_bfloat16 hv[4], lv[4];
    split_bf(v.x, hv[0], lv[0]); split_bf(v.y, hv[1], lv[1]);
    split_bf(v.z, hv[2], lv[2]); split_bf(v.w, hv[3], lv[3]);
    *(uint2*)dh = *(uint2*)hv;
    *(uint2*)dl = *(uint2*)lv;
}

// ---------------------------------------------------------------------------
// Split-bf16 mma.sync GEMM: 3-stage cp.async.ca pipeline, BK=32.
// ---------------------------------------------------------------------------
#define HSTR 40
#define MAT_HALVES (128*HSTR)
#define BUF_HALVES (4*MAT_HALVES)
#define GSTAGES 3
#define GEMM_DYN_SMEM (GSTAGES*BUF_HALVES*2)   // 122880 B

__global__ __launch_bounds__(256, 1)
void gemm_bf16_kernel(const __nv_bfloat16* __restrict__ Ah, const __nv_bfloat16* __restrict__ Al,
                      const __nv_bfloat16* __restrict__ Bh, const __nv_bfloat16* __restrict__ Bl,
                      const float* __restrict__ bias0, const float* __restrict__ bias1,
                      const float* __restrict__ bias2,
                      float* __restrict__ Cout, int mode)
{
    extern __shared__ __nv_bfloat16 sm[];

    const int tid  = threadIdx.x;
    const int wid  = tid >> 5;
    const int lane = tid & 31;
    const int warp_m = wid >> 2;
    const int warp_n = wid & 3;
    const int m0 = blockIdx.y * 128;
    const int n0 = blockIdx.x * 128;
    const int which = n0 >> 10;
    const int n0m = n0 & 1023;
    const float* biasm = (which == 0) ? bias0 : (which == 1) ? bias1 : bias2;

    float acc[4][4][4];
#pragma unroll
    for (int f = 0; f < 4; f++)
#pragma unroll
        for (int g = 0; g < 4; g++)
#pragma unroll
            for (int e = 0; e < 4; e++) acc[f][g][e] = 0.f;

    const int lrow = tid >> 2;          // 0..63
    const int lk   = (tid & 3) * 8;     // 0,8,16,24
    const uint32_t smb = smem_u32(sm);

    // async-issue chunk c into stage buffer (c % GSTAGES)
    auto issue = [&](int c) {
        uint32_t bb = smb + (c % GSTAGES) * BUF_HALVES * 2;
        int kg = c * 32 + lk;
#pragma unroll
        for (int i = 0; i < 2; i++) {
            int row = lrow + i * 64;
            uint32_t doff = (row * HSTR + lk) * 2;
            CPA16(bb + 0 * MAT_HALVES * 2 + doff, Ah + (size_t)(m0 + row) * 1024 + kg);
            CPA16(bb + 1 * MAT_HALVES * 2 + doff, Al + (size_t)(m0 + row) * 1024 + kg);
            CPA16(bb + 2 * MAT_HALVES * 2 + doff, Bh + (size_t)(n0 + row) * 1024 + kg);
            CPA16(bb + 3 * MAT_HALVES * 2 + doff, Bl + (size_t)(n0 + row) * 1024 + kg);
        }
        CP_COMMIT();
    };

    issue(0);
    issue(1);

    const int a_r   = lane & 15;
    const int a_kof = (lane >> 4) * 8;

    for (int c = 0; c < 32; c++) {
        if (c < 31) CP_WAIT1(); else CP_WAIT0();   // stage c complete
        __syncthreads();
        if (c + 2 < 32) issue(c + 2);              // overlaps compute(c)

        __nv_bfloat16* cb = sm + (c % GSTAGES) * BUF_HALVES;
#pragma unroll
        for (int ks = 0; ks < 2; ks++) {
            uint32_t aH[4][4], aL[4][4], bH[2][4], bL[2][4];
#pragma unroll
            for (int f = 0; f < 4; f++) {
                int row = warp_m * 64 + f * 16 + a_r;
                uint32_t addrH = smem_u32(&cb[0 * MAT_HALVES + row * HSTR + ks * 16 + a_kof]);
                LDMATRIX_X4(aH[f][0], aH[f][1], aH[f][2], aH[f][3], addrH);
                uint32_t addrL = smem_u32(&cb[1 * MAT_HALVES + row * HSTR + ks * 16 + a_kof]);
                LDMATRIX_X4(aL[f][0], aL[f][1], aL[f][2], aL[f][3], addrL);
            }
            ldmB(&cb[2 * MAT_HALVES], HSTR, warp_n * 32 +  0, ks * 16, lane, bH[0]);
            ldmB(&cb[2 * MAT_HALVES], HSTR, warp_n * 32 + 16, ks * 16, lane, bH[1]);
            ldmB(&cb[3 * MAT_HALVES], HSTR, warp_n * 32 +  0, ks * 16, lane, bL[0]);
            ldmB(&cb[3 * MAT_HALVES], HSTR, warp_n * 32 + 16, ks * 16, lane, bL[1]);
#pragma unroll
            for (int f = 0; f < 4; f++)
#pragma unroll
                for (int g = 0; g < 4; g++) {
                    const uint32_t* ph = &bH[g >> 1][(g & 1) * 2];
                    const uint32_t* pls = &bL[g >> 1][(g & 1) * 2];
                    MMA_BF16(acc[f][g], aH[f], ph);
                    MMA_BF16(acc[f][g], aH[f], pls);
                    MMA_BF16(acc[f][g], aL[f], ph);
                }
        }
        __syncthreads();   // all warps done with stage c before issue(c+3)
    }

    if (mode == 0) {
        const float scale = (which == 0) ? 0.125f : 1.0f;
#pragma unroll
        for (int f = 0; f < 4; f++) {
            int mrow0 = m0 + warp_m * 64 + f * 16 + (lane >> 2);
#pragma unroll
            for (int g = 0; g < 4; g++) {
                int ncol = n0m + warp_n * 32 + g * 8 + (lane & 3) * 2;
#pragma unroll
                for (int e = 0; e < 4; e++) {
                    int m = mrow0 + (e >> 1) * 8;
                    int nm = ncol + (e & 1);
                    int b = m >> 10, s = m & 1023;
                    int h = nm >> 6, d = nm & 63;
                    float val = (acc[f][g][e] + biasm[nm]) * scale;
                    __nv_bfloat16 vh, vl;
                    split_bf(val, vh, vl);
                    if (which == 2) {
                        size_t idx = ((size_t)(b * NH + h) * DK + d) * SEQ + s;
                        g_Vth[idx] = vh; g_Vtl[idx] = vl;
                    } else if (which == 0) {
                        size_t idx = ((size_t)(b * NH + h) * SEQ + s) * DK + d;
                        g_Qh[idx] = vh; g_Ql[idx] = vl;
                    } else {
                        size_t idx = ((size_t)(b * NH + h) * SEQ + s) * DK + d;
                        g_Kh[idx] = vh; g_Kl[idx] = vl;
                    }
                }
            }
        }
    } else {
#pragma unroll
        for (int f = 0; f < 4; f++) {
            int mrow0 = m0 + warp_m * 64 + f * 16 + (lane >> 2);
#pragma unroll
            for (int g = 0; g < 4; g++) {
                int ncol = n0 + warp_n * 32 + g * 8 + (lane & 3) * 2;
#pragma unroll
                for (int e = 0; e < 4; e++) {
                    int m = mrow0 + (e >> 1) * 8;
                    int n = ncol + (e & 1);
                    Cout[(size_t)m * D_MODEL + n] = acc[f][g][e] + biasm[n];
                }
            }
        }
    }
}

// ---------------------------------------------------------------------------
// Pipelined MMA flash-attention (unchanged from R7 / 414 µs baseline).
// ---------------------------------------------------------------------------
#define ASTR  72
#define GBSTR 84
#define ST_KH 0
#define ST_KL (64*ASTR)
#define ST_VH (2*64*ASTR)
#define ST_VL (3*64*ASTR)
#define ST_EH (4*64*ASTR)
#define ST_EL (4*64*ASTR + 192*ASTR)
#define STAGE_HALVES (4*64*ASTR + 2*192*ASTR)    // 46080 halves = 92160 B
#define G_OFF_HALVES (2*STAGE_HALVES)
#define ATTN_SMEM (G_OFF_HALVES*2 + 8*16*GBSTR*4)  // 227328 B

__device__ __forceinline__ void attn_issue_tile(
    uint32_t smb, int jt, int stg, int tid, int i0,
    const __nv_bfloat16* Khg, const __nv_bfloat16* Klg,
    const __nv_bfloat16* Vhg, const __nv_bfloat16* Vlg)
{
    const int j0 = jt * 64;
    const uint32_t base = smb + stg * STAGE_HALVES * 2;
    for (int t = tid; t < 512; t += 256) {
        int r = t >> 3, c8 = (t & 7) * 8;
        uint32_t doff = (r * ASTR + c8) * 2;
        CPA16(base + ST_KH * 2 + doff, Khg + (size_t)(j0 + r) * DK + c8);
        CPA16(base + ST_KL * 2 + doff, Klg + (size_t)(j0 + r) * DK + c8);
        CPA16(base + ST_VH * 2 + doff, Vhg + (size_t)r * SEQ + j0 + c8);
        CPA16(base + ST_VL * 2 + doff, Vlg + (size_t)r * SEQ + j0 + c8);
    }
    const int rbase = (SEQ - 1) + i0 - j0 - 63;
    for (int t = tid; t < 1536; t += 256) {
        int r = t >> 3, c8 = (t & 7) * 8;
        int er = rbase + r;
        er = (er > ELEN - 1) ? (ELEN - 1) : er;
        uint32_t doff = (r * ASTR + c8) * 2;
        CPA16(base + ST_EH * 2 + doff, g_Eh + (size_t)er * DK + c8);
        CPA16(base + ST_EL * 2 + doff, g_El + (size_t)er * DK + c8);
    }
    CP_COMMIT();
}

__global__ __launch_bounds__(256)
void attn_mma_kernel()
{
    extern __shared__ __nv_bfloat16 smh[];
    float* sG = (float*)(smh + G_OFF_HALVES);
    __nv_bfloat16* sQh = (__nv_bfloat16*)sG;
    __nv_bfloat16* sQl = sQh + 128 * ASTR;

    const int tid  = threadIdx.x;
    const int lane = tid & 31;
    const int w    = tid >> 5;
    const int bh = blockIdx.y;
    const int i0 = blockIdx.x * 128;
    const int b = bh >> 4, h = bh & 15;

    const __nv_bfloat16* Qhg = g_Qh + (size_t)bh * SEQ * DK;
    const __nv_bfloat16* Qlg = g_Ql + (size_t)bh * SEQ * DK;
    const __nv_bfloat16* Khg = g_Kh + (size_t)bh * SEQ * DK;
    const __nv_bfloat16* Klg = g_Kl + (size_t)bh * SEQ * DK;
    const __nv_bfloat16* Vhg = g_Vth + (size_t)bh * DK * SEQ;
    const __nv_bfloat16* Vlg = g_Vtl + (size_t)bh * DK * SEQ;
    const uint32_t smb = smem_u32(smh);

    for (int t = tid; t < 1024; t += 256) {
        int r = t >> 3, c8 = (t & 7) * 8;
        *(uint4*)&sQh[r * ASTR + c8] = *(const uint4*)(Qhg + (size_t)(i0 + r) * DK + c8);
        *(uint4*)&sQl[r * ASTR + c8] = *(const uint4*)(Qlg + (size_t)(i0 + r) * DK + c8);
    }
    __syncthreads();
    uint32_t qh[4][4], ql[4][4];
#pragma unroll
    for (int ks = 0; ks < 4; ks++) {
        uint32_t aH = smem_u32(&sQh[(w * 16 + (lane & 15)) * ASTR + ks * 16 + (lane >> 4) * 8]);
        LDMATRIX_X4(qh[ks][0], qh[ks][1], qh[ks][2], qh[ks][3], aH);
        uint32_t aL = smem_u32(&sQl[(w * 16 + (lane & 15)) * ASTR + ks * 16 + (lane >> 4) * 8]);
        LDMATRIX_X4(ql[ks][0], ql[ks][1], ql[ks][2], ql[ks][3], aL);
    }
    __syncthreads();

    attn_issue_tile(smb, 0, 0, tid, i0, Khg, Klg, Vhg, Vlg);

    float accO[8][4];
#pragma unroll
    for (int nf = 0; nf < 8; nf++)
#pragma unroll
        for (int e = 0; e < 4; e++) accO[nf][e] = 0.f;
    float rmax0 = -1e30f, rmax1 = -1e30f, rsum0 = 0.f, rsum1 = 0.f;

    const int r0 = lane >> 2;
    const int c0 = (lane & 3) * 2;
    float* sGw = sG + w * 16 * GBSTR;

    for (int jt = 0; jt < 16; jt++) {
        if (jt < 15) {
            attn_issue_tile(smb, jt + 1, (jt + 1) & 1, tid, i0, Khg, Klg, Vhg, Vlg);
            CP_WAIT1();
        } else {
            CP_WAIT0();
        }
        __syncthreads();

        __nv_bfloat16* st = smh + (jt & 1) * STAGE_HALVES;
        __nv_bfloat16* sKh = st + ST_KH;
        __nv_bfloat16* sKl = st + ST_KL;
        __nv_bfloat16* sVh = st + ST_VH;
        __nv_bfloat16* sVl = st + ST_VL;
        __nv_bfloat16* sEh = st + ST_EH;
        __nv_bfloat16* sEl = st + ST_EL;

        // ---- G = Q * Eband^T, band-limited: nf in [2w, 2w+10) ----
        float gac[10][4];
#pragma unroll
        for (int bi = 0; bi < 10; bi++)
#pragma unroll
            for (int e = 0; e < 4; e++) gac[bi][e] = 0.f;
#pragma unroll
        for (int ks = 0; ks < 4; ks++) {
#pragma unroll
            for (int bp = 0; bp < 5; bp++) {
                uint32_t eh4[4], el4[4];
                int row0 = (2 * w + 2 * bp) * 8;
                ldmB(sEh, ASTR, row0, ks * 16, lane, eh4);
                ldmB(sEl, ASTR, row0, ks * 16, lane, el4);
                MMA_BF16(gac[2 * bp], qh[ks], eh4);
                MMA_BF16(gac[2 * bp], qh[ks], el4);
                MMA_BF16(gac[2 * bp], ql[ks], eh4);
                MMA_BF16(gac[2 * bp + 1], qh[ks], eh4 + 2);
                MMA_BF16(gac[2 * bp + 1], qh[ks], el4 + 2);
                MMA_BF16(gac[2 * bp + 1], ql[ks], eh4 + 2);
            }
        }
#pragma unroll
        for (int bi = 0; bi < 10; bi++) {
            *(float2*)&sGw[r0 * GBSTR + bi * 8 + c0] = make_float2(gac[bi][0], gac[bi][1]);
            *(float2*)&sGw[(r0 + 8) * GBSTR + bi * 8 + c0] = make_float2(gac[bi][2], gac[bi][3]);
        }

        // ---- S = Q * K^T ----
        float s[8][4];
#pragma unroll
        for (int nf = 0; nf < 8; nf++)
#pragma unroll
            for (int e = 0; e < 4; e++) s[nf][e] = 0.f;
#pragma unroll
        for (int ks = 0; ks < 4; ks++) {
#pragma unroll
            for (int gp = 0; gp < 4; gp++) {
                uint32_t kh4[4], kl4[4];
                ldmB(sKh, ASTR, gp * 16, ks * 16, lane, kh4);
                ldmB(sKl, ASTR, gp * 16, ks * 16, lane, kl4);
                MMA_BF16(s[2 * gp], qh[ks], kh4);
                MMA_BF16(s[2 * gp], qh[ks], kl4);
                MMA_BF16(s[2 * gp], ql[ks], kh4);
                MMA_BF16(s[2 * gp + 1], qh[ks], kh4 + 2);
                MMA_BF16(s[2 * gp + 1], qh[ks], kl4 + 2);
                MMA_BF16(s[2 * gp + 1], ql[ks], kh4 + 2);
            }
        }
        __syncwarp();

        // ---- gather BD from G band and add ----
#pragma unroll
        for (int nf = 0; nf < 8; nf++)
#pragma unroll
            for (int e = 0; e < 4; e++) {
                int iw = r0 + ((e >> 1) << 3);
                int jl = nf * 8 + c0 + (e & 1);
                s[nf][e] += sGw[iw * GBSTR + (iw - jl + 63)];
            }

        // ---- online softmax ----
        float mx0 = -1e30f, mx1 = -1e30f;
#pragma unroll
        for (int nf = 0; nf < 8; nf++) {
            mx0 = fmaxf(mx0, fmaxf(s[nf][0], s[nf][1]));
            mx1 = fmaxf(mx1, fmaxf(s[nf][2], s[nf][3]));
        }
#pragma unroll
        for (int o = 1; o <= 2; o <<= 1) {
            mx0 = fmaxf(mx0, __shfl_xor_sync(0xffffffffu, mx0, o));
            mx1 = fmaxf(mx1, __shfl_xor_sync(0xffffffffu, mx1, o));
        }
        float nm0 = fmaxf(rmax0, mx0), nm1 = fmaxf(rmax1, mx1);
        float al0 = __expf(rmax0 - nm0), al1 = __expf(rmax1 - nm1);
        rmax0 = nm0; rmax1 = nm1;
        float ls0 = 0.f, ls1 = 0.f;
#pragma unroll
        for (int nf = 0; nf < 8; nf++) {
            s[nf][0] = __expf(s[nf][0] - nm0);
            s[nf][1] = __expf(s[nf][1] - nm0);
            s[nf][2] = __expf(s[nf][2] - nm1);
            s[nf][3] = __expf(s[nf][3] - nm1);
            ls0 += s[nf][0] + s[nf][1];
            ls1 += s[nf][2] + s[nf][3];
        }
#pragma unroll
        for (int o = 1; o <= 2; o <<= 1) {
            ls0 += __shfl_xor_sync(0xffffffffu, ls0, o);
            ls1 += __shfl_xor_sync(0xffffffffu, ls1, o);
        }
        rsum0 = rsum0 * al0 + ls0;
        rsum1 = rsum1 * al1 + ls1;
#pragma unroll
        for (int nf = 0; nf < 8; nf++) {
            accO[nf][0] *= al0; accO[nf][1] *= al0;
            accO[nf][2] *= al1; accO[nf][3] *= al1;
        }

        // ---- pack P fragments (hi + residual-lo) ----
        uint32_t ph[4][4], pl[4][4];
#pragma unroll
        for (int ks = 0; ks < 4; ks++) {
            int f0 = 2 * ks, f1 = 2 * ks + 1;
            float rlo[8];
#pragma unroll
            for (int e = 0; e < 4; e++) {
                rlo[e]     = s[f0][e] - __bfloat162float(__float2bfloat16_rn(s[f0][e]));
                rlo[4 + e] = s[f1][e] - __bfloat162float(__float2bfloat16_rn(s[f1][e]));
            }
            ph[ks][0] = pack_bf2(s[f0][0], s[f0][1]);
            ph[ks][1] = pack_bf2(s[f0][2], s[f0][3]);
            ph[ks][2] = pack_bf2(s[f1][0], s[f1][1]);
            ph[ks][3] = pack_bf2(s[f1][2], s[f1][3]);
            pl[ks][0] = pack_bf2(rlo[0], rlo[1]);
            pl[ks][1] = pack_bf2(rlo[2], rlo[3]);
            pl[ks][2] = pack_bf2(rlo[4], rlo[5]);
            pl[ks][3] = pack_bf2(rlo[6], rlo[7]);
        }

        // ---- O += P * V ----
#pragma unroll
        for (int ks = 0; ks < 4; ks++) {
#pragma unroll
            for (int gp = 0; gp < 4; gp++) {
                uint32_t vh4[4], vl4[4];
                ldmB(sVh, ASTR, gp * 16, ks * 16, lane, vh4);
                ldmB(sVl, ASTR, gp * 16, ks * 16, lane, vl4);
                MMA_BF16(accO[2 * gp], ph[ks], vh4);
                MMA_BF16(accO[2 * gp], ph[ks], vl4);
                MMA_BF16(accO[2 * gp], pl[ks], vh4);
                MMA_BF16(accO[2 * gp + 1], ph[ks], vh4 + 2);
                MMA_BF16(accO[2 * gp + 1], ph[ks], vl4 + 2);
                MMA_BF16(accO[2 * gp + 1], pl[ks], vh4 + 2);
            }
        }
        __syncthreads();
    }

    // ---- epilogue ----
    float inv0 = 1.0f / rsum0, inv1 = 1.0f / rsum1;
#pragma unroll
    for (int nf = 0; nf < 8; nf++)
#pragma unroll
        for (int e = 0; e < 4; e++) {
            int i = i0 + w * 16 + r0 + ((e >> 1) << 3);
            int d = nf * 8 + c0 + (e & 1);
            float v = accO[nf][e] * ((e < 2) ? inv0 : inv1);
            __nv_bfloat16 vh, vl;
            split_bf(v, vh, vl);
            size_t idx = ((size_t)(b * SEQ + i)) * D_MODEL + h * DK + d;
            g_oh[idx] = vh; g_ol[idx] = vl;
        }
}

// ---------------------------------------------------------------------------
extern "C" void kernel_launch(void* const* d_in, const int* in_sizes, int n_in,
                              void* d_out, int out_size)
{
    const float* x  = (const float*)d_in[0];
    const float* Wq = (const float*)d_in[1];
    const float* bq = (const float*)d_in[2];
    const float* Wk = (const float*)d_in[3];
    const float* bk = (const float*)d_in[4];
    const float* Wv = (const float*)d_in[5];
    const float* bv = (const float*)d_in[6];
    const float* Wo = (const float*)d_in[7];
    const float* bo = (const float*)d_in[8];
    const float* Er = (const float*)d_in[9];
    float* out = (float*)d_out;

    cudaFuncSetAttribute(gemm_bf16_kernel,
                         cudaFuncAttributeMaxDynamicSharedMemorySize, GEMM_DYN_SMEM);
    cudaFuncSetAttribute(attn_mma_kernel,
                         cudaFuncAttributeMaxDynamicSharedMemorySize, ATTN_SMEM);

    __nv_bfloat16 *xh, *xl, *wh, *wl, *oh, *ol;
    cudaGetSymbolAddress((void**)&xh, g_xh);
    cudaGetSymbolAddress((void**)&xl, g_xl);
    cudaGetSymbolAddress((void**)&wh, g_wh);
    cudaGetSymbolAddress((void**)&wl, g_wl);
    cudaGetSymbolAddress((void**)&oh, g_oh);
    cudaGetSymbolAddress((void**)&ol, g_ol);

    // 0) split x, weights, Er into bf16 hi/lo
    {
        int total = (MTOT * D_MODEL + 4 * D_MODEL * D_MODEL + ELEN * DK) / 4;
        convert_xw_kernel<<<(total + 255) / 256, 256>>>(x, Wq, Wk, Wv, Wo, Er);
    }
    // 1) fused QKV projection -> split-bf16 Q/K (head-major) + V^T
    {
        dim3 grid(3072 / 128, MTOT / 128);
        gemm_bf16_kernel<<<grid, 256, GEMM_DYN_SMEM>>>(
            xh, xl, wh, wl, bq, bk, bv, nullptr, 0);
    }
    // 2) pipelined MMA attention -> split-bf16 O
    {
        dim3 grid(SEQ / 128, BHT);           // 8 x 32
        attn_mma_kernel<<<grid, 256, ATTN_SMEM>>>();
    }
    // 3) output projection -> out
    {
        dim3 grid(D_MODEL / 128, MTOT / 128);
        gemm_bf16_kernel<<<grid, 256, GEMM_DYN_SMEM>>>(
            oh, ol, wh + (size_t)3 * D_MODEL * D_MODEL, wl + (size_t)3 * D_MODEL * D_MODEL,
            bo, bo, bo, out, 1);
    }
}